// round 4
// baseline (speedup 1.0000x reference)
#include <cuda_runtime.h>
#include <cuda_bf16.h>
#include <math.h>
#include <stdint.h>

// Problem constants (fixed by the reference)
#define BS 2
#define NQ 21760
#define NV 21760
#define MROWS (BS * NQ)   // 43520

__device__ __constant__ int LVL_W[4] = {128, 64, 32, 16};
__device__ __constant__ int LVL_S[4] = {0, 16384, 20480, 21504};

// Scratch (allocation-free rule: __device__ globals)
__device__ float g_val [MROWS * 256];
__device__ float g_off [MROWS * 256];
__device__ float g_attn[MROWS * 128];
__device__ float g_samp[MROWS * 256];

// ---------------------------------------------------------------------------
// Split-precision bf16 GEMM on the tensor pipe.
// C[M,N] = A[M,256] @ B[256,N] + bias[N], fp32 in/out.
// v = hi(v)+lo(v) in bf16; product = hh + hl + lh (ll dropped) -> ~1e-5 err.
// Tile 128x128, BK=16, 256 threads, warp tile 64x32, mma.m16n8k16.
// A is staged in smem in EXACT fragment order so compute uses LDS.128.
// ---------------------------------------------------------------------------
#define BSTRIDE 136   // words per B-kpair row in smem (128 used + 8 pad)

__device__ __forceinline__ void split2(float x, float y, uint32_t &hi, uint32_t &lo) {
    __nv_bfloat16 hx = __float2bfloat16_rn(x);
    __nv_bfloat16 hy = __float2bfloat16_rn(y);
    __nv_bfloat16 lx = __float2bfloat16_rn(x - __bfloat162float(hx));
    __nv_bfloat16 ly = __float2bfloat16_rn(y - __bfloat162float(hy));
    hi = ((uint32_t)__bfloat16_as_ushort(hy) << 16) | (uint32_t)__bfloat16_as_ushort(hx);
    lo = ((uint32_t)__bfloat16_as_ushort(ly) << 16) | (uint32_t)__bfloat16_as_ushort(lx);
}

__device__ __forceinline__ void mma_bf16(float *d, const uint32_t *a, const uint32_t *b) {
    asm volatile(
        "mma.sync.aligned.m16n8k16.row.col.f32.bf16.bf16.f32 "
        "{%0,%1,%2,%3}, {%4,%5,%6,%7}, {%8,%9}, {%0,%1,%2,%3};\n"
        : "+f"(d[0]), "+f"(d[1]), "+f"(d[2]), "+f"(d[3])
        : "r"(a[0]), "r"(a[1]), "r"(a[2]), "r"(a[3]), "r"(b[0]), "r"(b[1]));
}

__device__ __forceinline__ void gemm_body(
    const float* __restrict__ A, const float* __restrict__ B,
    const float* __restrict__ bias, float* __restrict__ C,
    int N, int bm, int bn)
{
    // A planes in fragment order: [rb(8)][g(8)][t(4)][q(4)] , q = (rowhalf + 2*khalf)
    __shared__ __align__(16) uint32_t Ah[2][1024];
    __shared__ __align__(16) uint32_t Al[2][1024];
    __shared__ __align__(16) uint32_t Bh[2][8 * BSTRIDE];
    __shared__ __align__(16) uint32_t Bl[2][8 * BSTRIDE];

    const int tid  = threadIdx.x;
    const int lane = tid & 31;
    const int warp = tid >> 5;
    const int g = lane >> 2;       // groupID (m row / n col within frag)
    const int t = lane & 3;        // threadID in group (kpair)
    const int warp_m16 = (warp >> 2) * 4;   // warp_m / 16
    const int warp_n = (warp & 3) * 32;

    // A staging mapping: tid -> (rb, sg, st2)
    const int s_rb = tid >> 5;          // 0..7 (16-row block)
    const int s_g  = (tid >> 2) & 7;    // row within block (and +8)
    const int s_t  = tid & 3;           // kpair (and +4)
    const int s_row = s_rb * 16 + s_g;
    const int s_base = s_rb * 128 + s_g * 16 + s_t * 4;
    // B staging mapping
    const int bk2 = tid >> 5;           // kpair row 0..7
    const int bn0 = (tid & 31) * 4;     // col 0..124

    float acc[4][4][4];
#pragma unroll
    for (int i = 0; i < 4; i++)
#pragma unroll
        for (int j = 0; j < 4; j++)
#pragma unroll
            for (int r = 0; r < 4; r++) acc[i][j][r] = 0.0f;

    float2 fa00, fa01, fa10, fa11;
    float4 b0r, b1r;

    // ---- load tile 0 to regs
    {
        const float* p0 = &A[(size_t)(bm + s_row) * 256 + 2 * s_t];
        fa00 = *(const float2*)p0;
        fa01 = *(const float2*)(p0 + 8);
        fa10 = *(const float2*)(p0 + 8 * 256);
        fa11 = *(const float2*)(p0 + 8 * 256 + 8);
        b0r = *(const float4*)&B[(size_t)(2 * bk2) * N + bn + bn0];
        b1r = *(const float4*)&B[(size_t)(2 * bk2 + 1) * N + bn + bn0];
    }
    // ---- convert + store tile 0 into buf 0
    {
        uint32_t q0h,q0l,q1h,q1l,q2h,q2l,q3h,q3l;
        split2(fa00.x, fa00.y, q0h, q0l);
        split2(fa10.x, fa10.y, q1h, q1l);
        split2(fa01.x, fa01.y, q2h, q2l);
        split2(fa11.x, fa11.y, q3h, q3l);
        *(uint4*)&Ah[0][s_base] = make_uint4(q0h, q1h, q2h, q3h);
        *(uint4*)&Al[0][s_base] = make_uint4(q0l, q1l, q2l, q3l);
        uint32_t h[4], l[4];
        float f0[4] = {b0r.x, b0r.y, b0r.z, b0r.w};
        float f1[4] = {b1r.x, b1r.y, b1r.z, b1r.w};
#pragma unroll
        for (int j = 0; j < 4; j++) split2(f0[j], f1[j], h[j], l[j]);
        *(uint4*)&Bh[0][bk2 * BSTRIDE + bn0] = make_uint4(h[0], h[1], h[2], h[3]);
        *(uint4*)&Bl[0][bk2 * BSTRIDE + bn0] = make_uint4(l[0], l[1], l[2], l[3]);
    }
    __syncthreads();

    for (int it = 0; it < 16; it++) {
        const int cur = it & 1;
        if (it < 15) {
            const int k0 = (it + 1) * 16;
            const float* p0 = &A[(size_t)(bm + s_row) * 256 + k0 + 2 * s_t];
            fa00 = *(const float2*)p0;
            fa01 = *(const float2*)(p0 + 8);
            fa10 = *(const float2*)(p0 + 8 * 256);
            fa11 = *(const float2*)(p0 + 8 * 256 + 8);
            b0r = *(const float4*)&B[(size_t)(k0 + 2 * bk2) * N + bn + bn0];
            b1r = *(const float4*)&B[(size_t)(k0 + 2 * bk2 + 1) * N + bn + bn0];
        }

        // ---- compute (one k16 step)
        {
            uint32_t afh[4][4], afl[4][4], bfh[4][2], bfl[4][2];
#pragma unroll
            for (int mt = 0; mt < 4; mt++) {
                uint4 ah = *(const uint4*)&Ah[cur][(warp_m16 + mt) * 128 + g * 16 + t * 4];
                uint4 al = *(const uint4*)&Al[cur][(warp_m16 + mt) * 128 + g * 16 + t * 4];
                afh[mt][0] = ah.x; afh[mt][1] = ah.y; afh[mt][2] = ah.z; afh[mt][3] = ah.w;
                afl[mt][0] = al.x; afl[mt][1] = al.y; afl[mt][2] = al.z; afl[mt][3] = al.w;
            }
#pragma unroll
            for (int nt = 0; nt < 4; nt++) {
                int cb = warp_n + nt * 8 + g;
                bfh[nt][0] = Bh[cur][t * BSTRIDE + cb];
                bfh[nt][1] = Bh[cur][(t + 4) * BSTRIDE + cb];
                bfl[nt][0] = Bl[cur][t * BSTRIDE + cb];
                bfl[nt][1] = Bl[cur][(t + 4) * BSTRIDE + cb];
            }
#pragma unroll
            for (int mt = 0; mt < 4; mt++)
#pragma unroll
                for (int nt = 0; nt < 4; nt++) {
                    mma_bf16(acc[mt][nt], afl[mt], bfh[nt]);
                    mma_bf16(acc[mt][nt], afh[mt], bfl[nt]);
                    mma_bf16(acc[mt][nt], afh[mt], bfh[nt]);
                }
        }

        if (it < 15) {
            const int nxt = cur ^ 1;
            uint32_t q0h,q0l,q1h,q1l,q2h,q2l,q3h,q3l;
            split2(fa00.x, fa00.y, q0h, q0l);
            split2(fa10.x, fa10.y, q1h, q1l);
            split2(fa01.x, fa01.y, q2h, q2l);
            split2(fa11.x, fa11.y, q3h, q3l);
            *(uint4*)&Ah[nxt][s_base] = make_uint4(q0h, q1h, q2h, q3h);
            *(uint4*)&Al[nxt][s_base] = make_uint4(q0l, q1l, q2l, q3l);
            uint32_t h[4], l[4];
            float f0[4] = {b0r.x, b0r.y, b0r.z, b0r.w};
            float f1[4] = {b1r.x, b1r.y, b1r.z, b1r.w};
#pragma unroll
            for (int j = 0; j < 4; j++) split2(f0[j], f1[j], h[j], l[j]);
            *(uint4*)&Bh[nxt][bk2 * BSTRIDE + bn0] = make_uint4(h[0], h[1], h[2], h[3]);
            *(uint4*)&Bl[nxt][bk2 * BSTRIDE + bn0] = make_uint4(l[0], l[1], l[2], l[3]);
            __syncthreads();
        }
    }

    // ---- epilogue: add bias, write fp32
#pragma unroll
    for (int mt = 0; mt < 4; mt++) {
        int row0 = bm + warp_m16 * 16 + mt * 16 + g;
#pragma unroll
        for (int nt = 0; nt < 4; nt++) {
            int col = bn + warp_n + nt * 8 + 2 * t;
            float2 bv = *(const float2*)&bias[col];
            float2 v0 = {acc[mt][nt][0] + bv.x, acc[mt][nt][1] + bv.y};
            float2 v1 = {acc[mt][nt][2] + bv.x, acc[mt][nt][3] + bv.y};
            *(float2*)&C[(size_t)row0 * N + col] = v0;
            *(float2*)&C[(size_t)(row0 + 8) * N + col] = v1;
        }
    }
}

__global__ __launch_bounds__(256)
void gemm_bf16split(const float* __restrict__ A, const float* __restrict__ B,
                    const float* __restrict__ bias, float* __restrict__ C, int N)
{
    gemm_body(A, B, bias, C, N, blockIdx.x * 128, blockIdx.y * 128);
}

// Merged launch: y<2 -> off GEMM (N=256), y==2 -> attn GEMM (N=128)
__global__ __launch_bounds__(256)
void gemm_off_attn(const float* __restrict__ query,
                   const float* __restrict__ W_off, const float* __restrict__ b_off,
                   float* __restrict__ c_off,
                   const float* __restrict__ W_att, const float* __restrict__ b_att,
                   float* __restrict__ c_att)
{
    const float *B, *bias; float *C; int N, bn;
    if (blockIdx.y < 2) { B = W_off; bias = b_off; C = c_off; N = 256; bn = blockIdx.y * 128; }
    else                { B = W_att; bias = b_att; C = c_att; N = 128; bn = 0; }
    gemm_body(query, B, bias, C, N, blockIdx.x * 128, bn);
}

// ---------------------------------------------------------------------------
// Deformable sampler v3: one warp per (b, q, h).
// Lanes 0..15 precompute each point's 4 corner byte-offsets (clamped) and 4
// masked weights; stored interleaved (idx,w) pairs in smem.
// Main loop: lane = (corner c = lane>>3, chan-group u = lane&7);
// per point: 1 LDS.64 + 1 LDG.128 + 4 FMA. Cross-corner shuffle reduce at end.
// ---------------------------------------------------------------------------
__global__ __launch_bounds__(256)
void sampler(const float* __restrict__ val, const float* __restrict__ off,
             const float* __restrict__ logits, const float* __restrict__ refp,
             float* __restrict__ out) {
    __shared__ __align__(16) float sm[8][16][8];  // [warp][point][(idx,w) x 4 corners]
    const unsigned FULL = 0xffffffffu;
    const int warp = threadIdx.x >> 5;
    const int lane = threadIdx.x & 31;
    const int wid  = blockIdx.x * 8 + warp;

    const int h  = wid & 7;
    const int bq = wid >> 3;
    const int b  = (bq >= NQ) ? 1 : 0;

    // coalesced loads
    float myoff = off[(size_t)bq * 256 + h * 32 + lane];
    float logit = (lane < 16) ? logits[(size_t)bq * 128 + h * 16 + lane] : -1e30f;
    float myref = (lane < 8)  ? refp[(size_t)bq * 8 + lane] : 0.0f;

    // softmax over 16 logits
    float m = logit;
#pragma unroll
    for (int o = 8; o > 0; o >>= 1) m = fmaxf(m, __shfl_xor_sync(FULL, m, o));
    float e = (lane < 16) ? __expf(logit - m) : 0.0f;
    float s = e;
#pragma unroll
    for (int o = 8; o > 0; o >>= 1) s += __shfl_xor_sync(FULL, s, o);
    float aw = e / s;

    // per-point precompute on lanes 0..15
    {
        int p = lane & 15;
        int l = p >> 2;
        float ox = __shfl_sync(FULL, myoff, 2 * p);
        float oy = __shfl_sync(FULL, myoff, 2 * p + 1);
        float rx = __shfl_sync(FULL, myref, 2 * l);
        float ry = __shfl_sync(FULL, myref, 2 * l + 1);

        const int Wl = LVL_W[l];
        const int st = LVL_S[l];
        float x = rx * (float)Wl + ox - 0.5f;
        float y = ry * (float)Wl + oy - 0.5f;   // H == W for all levels
        float xf = floorf(x), yf = floorf(y);
        int x0 = (int)xf, y0 = (int)yf;
        float fx = x - xf, fy = y - yf;

        float w00 = (1.0f - fx) * (1.0f - fy) * aw;
        float w10 = fx * (1.0f - fy) * aw;
        float w01 = (1.0f - fx) * fy * aw;
        float w11 = fx * fy * aw;

        bool vx0 = (x0 >= 0) && (x0 < Wl);
        bool vx1 = (x0 + 1 >= 0) && (x0 + 1 < Wl);
        bool vy0 = (y0 >= 0) && (y0 < Wl);
        bool vy1 = (y0 + 1 >= 0) && (y0 + 1 < Wl);
        w00 = (vx0 && vy0) ? w00 : 0.0f;
        w10 = (vx1 && vy0) ? w10 : 0.0f;
        w01 = (vx0 && vy1) ? w01 : 0.0f;
        w11 = (vx1 && vy1) ? w11 : 0.0f;

        int xc0 = min(max(x0, 0), Wl - 1);
        int xc1 = min(max(x0 + 1, 0), Wl - 1);
        int yc0 = min(max(y0, 0), Wl - 1);
        int yc1 = min(max(y0 + 1, 0), Wl - 1);

        // byte offsets: element idx * 256 floats * 4B = << 10
        int i00 = (st + yc0 * Wl + xc0) << 10;
        int i10 = (st + yc0 * Wl + xc1) << 10;
        int i01 = (st + yc1 * Wl + xc0) << 10;
        int i11 = (st + yc1 * Wl + xc1) << 10;

        if (lane < 16) {
            *(float4*)&sm[warp][p][0] =
                make_float4(__int_as_float(i00), w00, __int_as_float(i10), w10);
            *(float4*)&sm[warp][p][4] =
                make_float4(__int_as_float(i01), w01, __int_as_float(i11), w11);
        }
    }
    __syncwarp();

    const int c = lane >> 3;         // corner id
    const int u = lane & 7;          // channel group (4 floats)
    const char* vb = (const char*)(val + (size_t)b * (NV * 256) + h * 32) + u * 16;

    float4 acc = make_float4(0.0f, 0.0f, 0.0f, 0.0f);
#pragma unroll
    for (int p = 0; p < 16; p++) {
        float2 pr = *(const float2*)&sm[warp][p][2 * c];
        float w = pr.y;
        float4 v = *(const float4*)(vb + __float_as_int(pr.x));
        acc.x = fmaf(w, v.x, acc.x);
        acc.y = fmaf(w, v.y, acc.y);
        acc.z = fmaf(w, v.z, acc.z);
        acc.w = fmaf(w, v.w, acc.w);
    }

    // reduce the 4 corner groups (lane bits 3,4)
#pragma unroll
    for (int o = 8; o <= 16; o <<= 1) {
        acc.x += __shfl_xor_sync(FULL, acc.x, o);
        acc.y += __shfl_xor_sync(FULL, acc.y, o);
        acc.z += __shfl_xor_sync(FULL, acc.z, o);
        acc.w += __shfl_xor_sync(FULL, acc.w, o);
    }

    if (lane < 8)
        *(float4*)&out[(size_t)bq * 256 + h * 32 + lane * 4] = acc;
}

// ---------------------------------------------------------------------------
// kernel_launch
// Inputs: 0 query, 1 value, 2 reference_points, 3 spatial_shapes,
// 4 W_off, 5 b_off, 6 W_attn, 7 b_attn, 8 W_v, 9 b_v, 10 W_out, 11 b_out
// ---------------------------------------------------------------------------
extern "C" void kernel_launch(void* const* d_in, const int* in_sizes, int n_in,
                              void* d_out, int out_size) {
    const float* query = (const float*)d_in[0];
    const float* value = (const float*)d_in[1];
    const float* refp  = (const float*)d_in[2];
    const float* W_off = (const float*)d_in[4];
    const float* b_off = (const float*)d_in[5];
    const float* W_att = (const float*)d_in[6];
    const float* b_att = (const float*)d_in[7];
    const float* W_v   = (const float*)d_in[8];
    const float* b_v   = (const float*)d_in[9];
    const float* W_out = (const float*)d_in[10];
    const float* b_out = (const float*)d_in[11];
    float* out = (float*)d_out;

    float *p_val, *p_off, *p_attn, *p_samp;
    cudaGetSymbolAddress((void**)&p_val,  g_val);
    cudaGetSymbolAddress((void**)&p_off,  g_off);
    cudaGetSymbolAddress((void**)&p_attn, g_attn);
    cudaGetSymbolAddress((void**)&p_samp, g_samp);

    dim3 blk(256);
    dim3 g256(MROWS / 128, 2);
    dim3 g3(MROWS / 128, 3);

    gemm_bf16split<<<g256, blk>>>(value, W_v, b_v, p_val, 256);
    gemm_off_attn<<<g3, blk>>>(query, W_off, b_off, p_off, W_att, b_att, p_attn);
    sampler<<<MROWS, blk>>>(p_val, p_off, p_attn, refp, p_samp);
    gemm_bf16split<<<g256, blk>>>(p_samp, W_out, b_out, out, 256);
}

// round 5
// speedup vs baseline: 1.2408x; 1.2408x over previous
#include <cuda_runtime.h>
#include <cuda_bf16.h>
#include <math.h>
#include <stdint.h>

// Problem constants (fixed by the reference)
#define BS 2
#define NQ 21760
#define NV 21760
#define MROWS (BS * NQ)   // 43520

__device__ __constant__ int LVL_W[4] = {128, 64, 32, 16};
__device__ __constant__ int LVL_S[4] = {0, 16384, 20480, 21504};

// ---------------- scratch (allocation-free rule: __device__ globals) --------
__device__ float g_val [MROWS * 256];   // value @ W_v (fp32, gathered by sampler)
__device__ float g_off [MROWS * 256];
__device__ float g_attn[MROWS * 128];

// bf16 hi/lo planes for GEMM A operands
__device__ __align__(16) __nv_bfloat16 g_qh[MROWS * 256], g_ql[MROWS * 256];
__device__ __align__(16) __nv_bfloat16 g_vh[MROWS * 256], g_vl[MROWS * 256];
__device__ __align__(16) __nv_bfloat16 g_sh[MROWS * 256], g_sl[MROWS * 256];

// k-pair-packed bf16 weight planes: word[kp*N+n] = (bf16 W[2kp+1][n] <<16) | bf16 W[2kp][n]
__device__ __align__(16) uint32_t gWv_h[128 * 256], gWv_l[128 * 256];
__device__ __align__(16) uint32_t gWo_h[128 * 256], gWo_l[128 * 256];
__device__ __align__(16) uint32_t gWa_h[128 * 128], gWa_l[128 * 128];
__device__ __align__(16) uint32_t gWu_h[128 * 256], gWu_l[128 * 256];

// ---------------------------------------------------------------------------
__device__ __forceinline__ void split2(float x, float y, uint32_t &hi, uint32_t &lo) {
    __nv_bfloat16 hx = __float2bfloat16_rn(x);
    __nv_bfloat16 hy = __float2bfloat16_rn(y);
    __nv_bfloat16 lx = __float2bfloat16_rn(x - __bfloat162float(hx));
    __nv_bfloat16 ly = __float2bfloat16_rn(y - __bfloat162float(hy));
    hi = ((uint32_t)__bfloat16_as_ushort(hy) << 16) | (uint32_t)__bfloat16_as_ushort(hx);
    lo = ((uint32_t)__bfloat16_as_ushort(ly) << 16) | (uint32_t)__bfloat16_as_ushort(lx);
}

__device__ __forceinline__ void mma_bf16(float *d, const uint32_t *a, const uint32_t *b) {
    asm volatile(
        "mma.sync.aligned.m16n8k16.row.col.f32.bf16.bf16.f32 "
        "{%0,%1,%2,%3}, {%4,%5,%6,%7}, {%8,%9}, {%0,%1,%2,%3};\n"
        : "+f"(d[0]), "+f"(d[1]), "+f"(d[2]), "+f"(d[3])
        : "r"(a[0]), "r"(a[1]), "r"(a[2]), "r"(a[3]), "r"(b[0]), "r"(b[1]));
}

__device__ __forceinline__ void ldsm4(uint32_t *r, uint32_t addr) {
    asm volatile("ldmatrix.sync.aligned.m8n8.x4.shared.b16 {%0,%1,%2,%3}, [%4];"
                 : "=r"(r[0]), "=r"(r[1]), "=r"(r[2]), "=r"(r[3]) : "r"(addr));
}

__device__ __forceinline__ void cp16(uint32_t dst, const void* src) {
    asm volatile("cp.async.cg.shared.global [%0], [%1], 16;\n" :: "r"(dst), "l"(src));
}
__device__ __forceinline__ void cp_commit() { asm volatile("cp.async.commit_group;\n"); }
__device__ __forceinline__ void cp_wait0()  { asm volatile("cp.async.wait_group 0;\n"); }

// ---------------------------------------------------------------------------
// Conversion kernels
// ---------------------------------------------------------------------------
#define ACT_WORDS (MROWS * 256 / 8)   // 8 floats per thread

__global__ __launch_bounds__(256)
void convert_acts(const float* __restrict__ query, const float* __restrict__ value) {
    int idx = blockIdx.x * 256 + threadIdx.x;
    const float* src; __nv_bfloat16 *H, *L;
    if (idx < ACT_WORDS) { src = query; H = g_qh; L = g_ql; }
    else { idx -= ACT_WORDS; src = value; H = g_vh; L = g_vl; }
    float4 f0 = *(const float4*)&src[idx * 8];
    float4 f1 = *(const float4*)&src[idx * 8 + 4];
    uint32_t h0,l0,h1,l1,h2,l2,h3,l3;
    split2(f0.x, f0.y, h0, l0);
    split2(f0.z, f0.w, h1, l1);
    split2(f1.x, f1.y, h2, l2);
    split2(f1.z, f1.w, h3, l3);
    *(uint4*)&H[idx * 8] = make_uint4(h0, h1, h2, h3);
    *(uint4*)&L[idx * 8] = make_uint4(l0, l1, l2, l3);
}

__global__ __launch_bounds__(256)
void convert_wts(const float* __restrict__ Wv, const float* __restrict__ Wo,
                 const float* __restrict__ Wa, const float* __restrict__ Wu) {
    int idx = blockIdx.x * 256 + threadIdx.x;
    const float* W; uint32_t *H, *L; int N;
    if (idx < 32768)      { W = Wv; H = gWv_h; L = gWv_l; N = 256; }
    else if (idx < 65536) { idx -= 32768; W = Wo; H = gWo_h; L = gWo_l; N = 256; }
    else if (idx < 81920) { idx -= 65536; W = Wa; H = gWa_h; L = gWa_l; N = 128; }
    else                  { idx -= 81920; W = Wu; H = gWu_h; L = gWu_l; N = 256; }
    int kp = idx / N, n = idx - kp * N;
    float e = W[(2 * kp) * N + n];
    float o = W[(2 * kp + 1) * N + n];
    uint32_t hi, lo;
    split2(e, o, hi, lo);
    H[kp * N + n] = hi;
    L[kp * N + n] = lo;
}

// ---------------------------------------------------------------------------
// GEMM: C[M,N] = A @ B + bias from pre-split bf16 planes.
// Tile 128x128, BK=16, 256 thr (8 warps, warp tile 64x32), cp.async pipeline,
// ldmatrix for A frags, scalar LDS for packed B. 3-pass split MMA.
// ---------------------------------------------------------------------------
// smem: A row stride 48B (24 bf16 slots: 16 used), buf stride 6144B
//       B row stride 544B (136 words: 128 used), buf stride 4352B
struct SmemGemm {
    uint32_t Ah[2][1536];   // [buf][128 rows * 12 words]
    uint32_t Al[2][1536];
    uint32_t Bh[2][1088];   // [buf][8 kpair rows * 136 words]
    uint32_t Bl[2][1088];
};

__device__ __forceinline__ void gemm_body(
    SmemGemm* sm,
    const __nv_bfloat16* __restrict__ Agh, const __nv_bfloat16* __restrict__ Agl,
    const uint32_t* __restrict__ Bgh, const uint32_t* __restrict__ Bgl,
    const float* __restrict__ bias, float* __restrict__ C,
    int N, int bm, int bn)
{
    const int tid  = threadIdx.x;
    const int lane = tid & 31;
    const int warp = tid >> 5;
    const int g = lane >> 2;
    const int t = lane & 3;
    const int warp_m = (warp >> 2) * 64;
    const int warp_n = (warp & 3) * 32;

    // cp.async staging mapping
    const int arow  = tid >> 1;
    const int ahalf = tid & 1;
    const int brow  = tid >> 5;
    const int bc    = tid & 31;

    const uint32_t sAh = (uint32_t)__cvta_generic_to_shared(sm->Ah);
    const uint32_t sAl = (uint32_t)__cvta_generic_to_shared(sm->Al);
    const uint32_t sBh = (uint32_t)__cvta_generic_to_shared(sm->Bh);
    const uint32_t sBl = (uint32_t)__cvta_generic_to_shared(sm->Bl);

    const uint32_t aDst = arow * 48 + ahalf * 16;
    const uint32_t bDst = brow * 544 + bc * 16;
    const __nv_bfloat16* aSrcH = Agh + (size_t)(bm + arow) * 256 + ahalf * 8;
    const __nv_bfloat16* aSrcL = Agl + (size_t)(bm + arow) * 256 + ahalf * 8;
    const uint32_t* bSrcH = Bgh + (size_t)brow * N + bn + bc * 4;
    const uint32_t* bSrcL = Bgl + (size_t)brow * N + bn + bc * 4;

    // ldmatrix per-lane base
    const int lr = (lane & 7) + ((lane >> 3) & 1) * 8;
    const int lb = (lane >> 4) * 16;
    const uint32_t aFH = sAh + (warp_m + lr) * 48 + lb;
    const uint32_t aFL = sAl + (warp_m + lr) * 48 + lb;

    float acc[4][4][4];
#pragma unroll
    for (int i = 0; i < 4; i++)
#pragma unroll
        for (int j = 0; j < 4; j++)
#pragma unroll
            for (int r = 0; r < 4; r++) acc[i][j][r] = 0.0f;

    // stage 0
    {
        cp16(sAh + aDst, aSrcH);
        cp16(sAl + aDst, aSrcL);
        cp16(sBh + bDst, bSrcH);
        cp16(sBl + bDst, bSrcL);
        cp_commit();
    }

    for (int it = 0; it < 16; it++) {
        const int cur = it & 1;
        cp_wait0();
        __syncthreads();
        if (it < 15) {
            const int nxt = (it + 1) & 1;
            const int k0 = (it + 1) * 16;
            cp16(sAh + nxt * 6144 + aDst, aSrcH + k0);
            cp16(sAl + nxt * 6144 + aDst, aSrcL + k0);
            cp16(sBh + nxt * 4352 + bDst, bSrcH + (size_t)(it + 1) * 8 * N);
            cp16(sBl + nxt * 4352 + bDst, bSrcL + (size_t)(it + 1) * 8 * N);
            cp_commit();
        }

        // B fragments (packed kpair words), conflict-free
        uint32_t bfh[4][2], bfl[4][2];
#pragma unroll
        for (int nt = 0; nt < 4; nt++) {
            int cb = warp_n + nt * 8 + g;
            bfh[nt][0] = sm->Bh[cur][t * 136 + cb];
            bfh[nt][1] = sm->Bh[cur][(t + 4) * 136 + cb];
            bfl[nt][0] = sm->Bl[cur][t * 136 + cb];
            bfl[nt][1] = sm->Bl[cur][(t + 4) * 136 + cb];
        }
        // per-mt: 2 ldmatrix + 12 MMA (keeps live A frags at 8 regs)
#pragma unroll
        for (int mt = 0; mt < 4; mt++) {
            uint32_t ah[4], al[4];
            ldsm4(ah, aFH + cur * 6144 + mt * 768);
            ldsm4(al, aFL + cur * 6144 + mt * 768);
#pragma unroll
            for (int nt = 0; nt < 4; nt++) {
                mma_bf16(acc[mt][nt], al, bfh[nt]);
                mma_bf16(acc[mt][nt], ah, bfl[nt]);
                mma_bf16(acc[mt][nt], ah, bfh[nt]);
            }
        }
    }

    // epilogue
#pragma unroll
    for (int mt = 0; mt < 4; mt++) {
        int row0 = bm + warp_m + mt * 16 + g;
#pragma unroll
        for (int nt = 0; nt < 4; nt++) {
            int col = bn + warp_n + nt * 8 + 2 * t;
            float2 bv = *(const float2*)&bias[col];
            float2 v0 = {acc[mt][nt][0] + bv.x, acc[mt][nt][1] + bv.y};
            float2 v1 = {acc[mt][nt][2] + bv.x, acc[mt][nt][3] + bv.y};
            *(float2*)&C[(size_t)row0 * N + col] = v0;
            *(float2*)&C[(size_t)(row0 + 8) * N + col] = v1;
        }
    }
}

__global__ __launch_bounds__(256, 2)
void gemm_val(const float* __restrict__ bias) {
    __shared__ SmemGemm sm;
    gemm_body(&sm, g_vh, g_vl, gWv_h, gWv_l, bias, g_val, 256,
              blockIdx.x * 128, blockIdx.y * 128);
}

__global__ __launch_bounds__(256, 2)
void gemm_qoa(const float* __restrict__ b_off, const float* __restrict__ b_att) {
    __shared__ SmemGemm sm;
    if (blockIdx.y < 2)
        gemm_body(&sm, g_qh, g_ql, gWo_h, gWo_l, b_off, g_off, 256,
                  blockIdx.x * 128, blockIdx.y * 128);
    else
        gemm_body(&sm, g_qh, g_ql, gWa_h, gWa_l, b_att, g_attn, 128,
                  blockIdx.x * 128, 0);
}

__global__ __launch_bounds__(256, 2)
void gemm_out(const float* __restrict__ bias, float* __restrict__ out) {
    __shared__ SmemGemm sm;
    gemm_body(&sm, g_sh, g_sl, gWu_h, gWu_l, bias, out, 256,
              blockIdx.x * 128, blockIdx.y * 128);
}

// ---------------------------------------------------------------------------
// Deformable sampler: one warp per (b, q, h); corner-parallel float4 gathers.
// Emits samp directly as bf16 hi/lo planes for the out-GEMM.
// ---------------------------------------------------------------------------
__global__ __launch_bounds__(256)
void sampler(const float* __restrict__ refp) {
    __shared__ __align__(16) float smp[8][16][8];
    const unsigned FULL = 0xffffffffu;
    const int warp = threadIdx.x >> 5;
    const int lane = threadIdx.x & 31;
    const int wid  = blockIdx.x * 8 + warp;

    const int h  = wid & 7;
    const int bq = wid >> 3;
    const int b  = (bq >= NQ) ? 1 : 0;

    float myoff = g_off[(size_t)bq * 256 + h * 32 + lane];
    float logit = (lane < 16) ? g_attn[(size_t)bq * 128 + h * 16 + lane] : -1e30f;
    float myref = (lane < 8)  ? refp[(size_t)bq * 8 + lane] : 0.0f;

    float m = logit;
#pragma unroll
    for (int o = 8; o > 0; o >>= 1) m = fmaxf(m, __shfl_xor_sync(FULL, m, o));
    float e = (lane < 16) ? __expf(logit - m) : 0.0f;
    float s = e;
#pragma unroll
    for (int o = 8; o > 0; o >>= 1) s += __shfl_xor_sync(FULL, s, o);
    float aw = e / s;

    {
        int p = lane & 15;
        int l = p >> 2;
        float ox = __shfl_sync(FULL, myoff, 2 * p);
        float oy = __shfl_sync(FULL, myoff, 2 * p + 1);
        float rx = __shfl_sync(FULL, myref, 2 * l);
        float ry = __shfl_sync(FULL, myref, 2 * l + 1);

        const int Wl = LVL_W[l];
        const int st = LVL_S[l];
        float x = rx * (float)Wl + ox - 0.5f;
        float y = ry * (float)Wl + oy - 0.5f;
        float xf = floorf(x), yf = floorf(y);
        int x0 = (int)xf, y0 = (int)yf;
        float fx = x - xf, fy = y - yf;

        float w00 = (1.0f - fx) * (1.0f - fy) * aw;
        float w10 = fx * (1.0f - fy) * aw;
        float w01 = (1.0f - fx) * fy * aw;
        float w11 = fx * fy * aw;

        bool vx0 = (x0 >= 0) && (x0 < Wl);
        bool vx1 = (x0 + 1 >= 0) && (x0 + 1 < Wl);
        bool vy0 = (y0 >= 0) && (y0 < Wl);
        bool vy1 = (y0 + 1 >= 0) && (y0 + 1 < Wl);
        w00 = (vx0 && vy0) ? w00 : 0.0f;
        w10 = (vx1 && vy0) ? w10 : 0.0f;
        w01 = (vx0 && vy1) ? w01 : 0.0f;
        w11 = (vx1 && vy1) ? w11 : 0.0f;

        int xc0 = min(max(x0, 0), Wl - 1);
        int xc1 = min(max(x0 + 1, 0), Wl - 1);
        int yc0 = min(max(y0, 0), Wl - 1);
        int yc1 = min(max(y0 + 1, 0), Wl - 1);

        int i00 = (st + yc0 * Wl + xc0) << 10;   // byte offsets (x256 floats x4B)
        int i10 = (st + yc0 * Wl + xc1) << 10;
        int i01 = (st + yc1 * Wl + xc0) << 10;
        int i11 = (st + yc1 * Wl + xc1) << 10;

        if (lane < 16) {
            *(float4*)&smp[warp][p][0] =
                make_float4(__int_as_float(i00), w00, __int_as_float(i10), w10);
            *(float4*)&smp[warp][p][4] =
                make_float4(__int_as_float(i01), w01, __int_as_float(i11), w11);
        }
    }
    __syncwarp();

    const int c = lane >> 3;
    const int u = lane & 7;
    const char* vb = (const char*)(g_val + (size_t)b * (NV * 256) + h * 32) + u * 16;

    float4 acc = make_float4(0.0f, 0.0f, 0.0f, 0.0f);
#pragma unroll
    for (int p = 0; p < 16; p++) {
        float2 pr = *(const float2*)&smp[warp][p][2 * c];
        float w = pr.y;
        float4 v = *(const float4*)(vb + __float_as_int(pr.x));
        acc.x = fmaf(w, v.x, acc.x);
        acc.y = fmaf(w, v.y, acc.y);
        acc.z = fmaf(w, v.z, acc.z);
        acc.w = fmaf(w, v.w, acc.w);
    }
#pragma unroll
    for (int o = 8; o <= 16; o <<= 1) {
        acc.x += __shfl_xor_sync(FULL, acc.x, o);
        acc.y += __shfl_xor_sync(FULL, acc.y, o);
        acc.z += __shfl_xor_sync(FULL, acc.z, o);
        acc.w += __shfl_xor_sync(FULL, acc.w, o);
    }

    if (lane < 8) {
        uint32_t h0,l0,h1,l1;
        split2(acc.x, acc.y, h0, l0);
        split2(acc.z, acc.w, h1, l1);
        size_t o8 = (size_t)bq * 256 + h * 32 + lane * 4;
        *(uint2*)&g_sh[o8] = make_uint2(h0, h1);
        *(uint2*)&g_sl[o8] = make_uint2(l0, l1);
    }
}

// ---------------------------------------------------------------------------
// kernel_launch
// Inputs: 0 query, 1 value, 2 reference_points, 3 spatial_shapes,
// 4 W_off, 5 b_off, 6 W_attn, 7 b_attn, 8 W_v, 9 b_v, 10 W_out, 11 b_out
// ---------------------------------------------------------------------------
extern "C" void kernel_launch(void* const* d_in, const int* in_sizes, int n_in,
                              void* d_out, int out_size) {
    const float* query = (const float*)d_in[0];
    const float* value = (const float*)d_in[1];
    const float* refp  = (const float*)d_in[2];
    const float* W_off = (const float*)d_in[4];
    const float* b_off = (const float*)d_in[5];
    const float* W_att = (const float*)d_in[6];
    const float* b_att = (const float*)d_in[7];
    const float* W_v   = (const float*)d_in[8];
    const float* b_v   = (const float*)d_in[9];
    const float* W_out = (const float*)d_in[10];
    const float* b_out = (const float*)d_in[11];
    float* out = (float*)d_out;

    dim3 blk(256);

    convert_acts<<<2 * (ACT_WORDS / 256), blk>>>(query, value);
    convert_wts<<<448, blk>>>(W_v, W_off, W_att, W_out);

    gemm_val<<<dim3(MROWS / 128, 2), blk>>>(b_v);
    gemm_qoa<<<dim3(MROWS / 128, 3), blk>>>(b_off, b_att);
    sampler<<<MROWS, blk>>>(refp);
    gemm_out<<<dim3(MROWS / 128, 2), blk>>>(b_out, out);
}

// round 9
// speedup vs baseline: 1.3236x; 1.0667x over previous
#include <cuda_runtime.h>
#include <cuda_bf16.h>
#include <math.h>
#include <stdint.h>

// Problem constants (fixed by the reference)
#define BS 2
#define NQ 21760
#define NV 21760
#define MROWS (BS * NQ)   // 43520

__device__ __constant__ int LVL_W[4] = {128, 64, 32, 16};
__device__ __constant__ int LVL_S[4] = {0, 16384, 20480, 21504};

// ---------------- scratch (allocation-free rule: __device__ globals) --------
__device__ float g_val [MROWS * 256];
__device__ float g_off [MROWS * 256];
__device__ float g_attn[MROWS * 128];

// bf16 hi/lo planes for GEMM A operands
__device__ __align__(16) __nv_bfloat16 g_qh[MROWS * 256], g_ql[MROWS * 256];
__device__ __align__(16) __nv_bfloat16 g_vh[MROWS * 256], g_vl[MROWS * 256];
__device__ __align__(16) __nv_bfloat16 g_sh[MROWS * 256], g_sl[MROWS * 256];

// k-pair-packed bf16 weight planes: word[kp*N+n] = (bf16 W[2kp+1][n] <<16) | bf16 W[2kp][n]
__device__ __align__(16) uint32_t gWv_h[128 * 256], gWv_l[128 * 256];
__device__ __align__(16) uint32_t gWo_h[128 * 256], gWo_l[128 * 256];
__device__ __align__(16) uint32_t gWa_h[128 * 128], gWa_l[128 * 128];
__device__ __align__(16) uint32_t gWu_h[128 * 256], gWu_l[128 * 256];

// ---------------------------------------------------------------------------
__device__ __forceinline__ void split2(float x, float y, uint32_t &hi, uint32_t &lo) {
    __nv_bfloat16 hx = __float2bfloat16_rn(x);
    __nv_bfloat16 hy = __float2bfloat16_rn(y);
    __nv_bfloat16 lx = __float2bfloat16_rn(x - __bfloat162float(hx));
    __nv_bfloat16 ly = __float2bfloat16_rn(y - __bfloat162float(hy));
    hi = ((uint32_t)__bfloat16_as_ushort(hy) << 16) | (uint32_t)__bfloat16_as_ushort(hx);
    lo = ((uint32_t)__bfloat16_as_ushort(ly) << 16) | (uint32_t)__bfloat16_as_ushort(lx);
}

__device__ __forceinline__ void mma_bf16(float *d, const uint32_t *a, const uint32_t *b) {
    asm volatile(
        "mma.sync.aligned.m16n8k16.row.col.f32.bf16.bf16.f32 "
        "{%0,%1,%2,%3}, {%4,%5,%6,%7}, {%8,%9}, {%0,%1,%2,%3};\n"
        : "+f"(d[0]), "+f"(d[1]), "+f"(d[2]), "+f"(d[3])
        : "r"(a[0]), "r"(a[1]), "r"(a[2]), "r"(a[3]), "r"(b[0]), "r"(b[1]));
}

__device__ __forceinline__ void ldsm4(uint32_t *r, uint32_t addr) {
    asm volatile("ldmatrix.sync.aligned.m8n8.x4.shared.b16 {%0,%1,%2,%3}, [%4];"
                 : "=r"(r[0]), "=r"(r[1]), "=r"(r[2]), "=r"(r[3]) : "r"(addr));
}

__device__ __forceinline__ void cp16(uint32_t dst, const void* src) {
    asm volatile("cp.async.cg.shared.global [%0], [%1], 16;\n" :: "r"(dst), "l"(src));
}
__device__ __forceinline__ void cp_commit() { asm volatile("cp.async.commit_group;\n"); }
__device__ __forceinline__ void cp_wait1() { asm volatile("cp.async.wait_group 1;\n"); }
__device__ __forceinline__ void cp_wait0() { asm volatile("cp.async.wait_group 0;\n"); }

// ---------------------------------------------------------------------------
// Conversion kernels
// ---------------------------------------------------------------------------
#define ACT_WORDS (MROWS * 256 / 8)

__global__ __launch_bounds__(256)
void convert_acts(const float* __restrict__ query, const float* __restrict__ value) {
    int idx = blockIdx.x * 256 + threadIdx.x;
    const float* src; __nv_bfloat16 *H, *L;
    if (idx < ACT_WORDS) { src = query; H = g_qh; L = g_ql; }
    else { idx -= ACT_WORDS; src = value; H = g_vh; L = g_vl; }
    float4 f0 = *(const float4*)&src[idx * 8];
    float4 f1 = *(const float4*)&src[idx * 8 + 4];
    uint32_t h0,l0,h1,l1,h2,l2,h3,l3;
    split2(f0.x, f0.y, h0, l0);
    split2(f0.z, f0.w, h1, l1);
    split2(f1.x, f1.y, h2, l2);
    split2(f1.z, f1.w, h3, l3);
    *(uint4*)&H[idx * 8] = make_uint4(h0, h1, h2, h3);
    *(uint4*)&L[idx * 8] = make_uint4(l0, l1, l2, l3);
}

__global__ __launch_bounds__(256)
void convert_wts(const float* __restrict__ Wv, const float* __restrict__ Wo,
                 const float* __restrict__ Wa, const float* __restrict__ Wu) {
    int idx = blockIdx.x * 256 + threadIdx.x;
    const float* W; uint32_t *H, *L; int N;
    if (idx < 32768)      { W = Wv; H = gWv_h; L = gWv_l; N = 256; }
    else if (idx < 65536) { idx -= 32768; W = Wo; H = gWo_h; L = gWo_l; N = 256; }
    else if (idx < 81920) { idx -= 65536; W = Wa; H = gWa_h; L = gWa_l; N = 128; }
    else                  { idx -= 81920; W = Wu; H = gWu_h; L = gWu_l; N = 256; }
    int kp = idx / N, n = idx - kp * N;
    float e = W[(2 * kp) * N + n];
    float o = W[(2 * kp + 1) * N + n];
    uint32_t hi, lo;
    split2(e, o, hi, lo);
    H[kp * N + n] = hi;
    L[kp * N + n] = lo;
}

// ---------------------------------------------------------------------------
// GEMM: C[M,N] = A @ B + bias from pre-split bf16 planes.
// Tile 128x128, BK=16, 256 thr (8 warps, warp tile 64x32).
// 3-stage cp.async pipeline (dynamic smem), ldmatrix A frags, scalar LDS B.
// 3-pass split MMA (hh + hl + lh).
// ---------------------------------------------------------------------------
// dynamic smem layout (bytes):
//   Ah: 3 bufs x 6144  @ 0        (128 rows x 48B: 32B used + 16B pad)
//   Al: 3 bufs x 6144  @ 18432
//   Bh: 3 bufs x 4352  @ 36864    (8 kpair rows x 544B: 512B used + 32B pad)
//   Bl: 3 bufs x 4352  @ 49920
#define A_BUF_B 6144
#define B_BUF_B 4352
#define OFF_AL 18432
#define OFF_BH 36864
#define OFF_BL 49920
#define DSMEM_BYTES 62976

__device__ __forceinline__ void gemm_body(
    const __nv_bfloat16* __restrict__ Agh, const __nv_bfloat16* __restrict__ Agl,
    const uint32_t* __restrict__ Bgh, const uint32_t* __restrict__ Bgl,
    const float* __restrict__ bias, float* __restrict__ C,
    int N, int bm, int bn)
{
    extern __shared__ __align__(128) char dsm[];
    const uint32_t sbase = (uint32_t)__cvta_generic_to_shared(dsm);

    const int tid  = threadIdx.x;
    const int lane = tid & 31;
    const int warp = tid >> 5;
    const int g = lane >> 2;
    const int t = lane & 3;
    const int warp_m = (warp >> 2) * 64;
    const int warp_n = (warp & 3) * 32;

    // cp.async staging mapping
    const int arow  = tid >> 1;
    const int ahalf = tid & 1;
    const int brow  = tid >> 5;
    const int bc    = tid & 31;

    const uint32_t aDst = arow * 48 + ahalf * 16;
    const uint32_t bDst = brow * 544 + bc * 16;
    const __nv_bfloat16* aSrcH = Agh + (size_t)(bm + arow) * 256 + ahalf * 8;
    const __nv_bfloat16* aSrcL = Agl + (size_t)(bm + arow) * 256 + ahalf * 8;
    const uint32_t* bSrcH = Bgh + (size_t)brow * N + bn + bc * 4;
    const uint32_t* bSrcL = Bgl + (size_t)brow * N + bn + bc * 4;

    // ldmatrix per-lane base (within one A plane/buffer)
    const int lr = (lane & 7) + ((lane >> 3) & 1) * 8;
    const int lb = (lane >> 4) * 16;
    const uint32_t aFrag = (warp_m + lr) * 48 + lb;

    float acc[4][4][4];
#pragma unroll
    for (int i = 0; i < 4; i++)
#pragma unroll
        for (int j = 0; j < 4; j++)
#pragma unroll
            for (int r = 0; r < 4; r++) acc[i][j][r] = 0.0f;

    // ---- stage loader (one BK=16 chunk into buffer `buf`)
    auto load_chunk = [&](int stage, int buf) {
        cp16(sbase + buf * A_BUF_B + aDst, aSrcH + stage * 16);
        cp16(sbase + OFF_AL + buf * A_BUF_B + aDst, aSrcL + stage * 16);
        cp16(sbase + OFF_BH + buf * B_BUF_B + bDst, bSrcH + (size_t)stage * 8 * N);
        cp16(sbase + OFF_BL + buf * B_BUF_B + bDst, bSrcL + (size_t)stage * 8 * N);
        cp_commit();
    };

    load_chunk(0, 0);
    load_chunk(1, 1);

#pragma unroll
    for (int it = 0; it < 16; it++) {
        const int buf = it % 3;
        if (it < 15) cp_wait1(); else cp_wait0();
        __syncthreads();
        if (it < 14) load_chunk(it + 2, (it + 2) % 3);

        // B fragments (packed kpair words), conflict-free
        const uint32_t* BhW = (const uint32_t*)(dsm + OFF_BH + buf * B_BUF_B);
        const uint32_t* BlW = (const uint32_t*)(dsm + OFF_BL + buf * B_BUF_B);
        uint32_t bfh[4][2], bfl[4][2];
#pragma unroll
        for (int nt = 0; nt < 4; nt++) {
            int cb = warp_n + nt * 8 + g;
            bfh[nt][0] = BhW[t * 136 + cb];
            bfh[nt][1] = BhW[(t + 4) * 136 + cb];
            bfl[nt][0] = BlW[t * 136 + cb];
            bfl[nt][1] = BlW[(t + 4) * 136 + cb];
        }
        // per-mt: 2 ldmatrix + 12 MMA
#pragma unroll
        for (int mt = 0; mt < 4; mt++) {
            uint32_t ah[4], al[4];
            ldsm4(ah, sbase + buf * A_BUF_B + aFrag + mt * 768);
            ldsm4(al, sbase + OFF_AL + buf * A_BUF_B + aFrag + mt * 768);
#pragma unroll
            for (int nt = 0; nt < 4; nt++) {
                mma_bf16(acc[mt][nt], al, bfh[nt]);
                mma_bf16(acc[mt][nt], ah, bfl[nt]);
                mma_bf16(acc[mt][nt], ah, bfh[nt]);
            }
        }
    }

    // epilogue
#pragma unroll
    for (int mt = 0; mt < 4; mt++) {
        int row0 = bm + warp_m + mt * 16 + g;
#pragma unroll
        for (int nt = 0; nt < 4; nt++) {
            int col = bn + warp_n + nt * 8 + 2 * t;
            float2 bv = *(const float2*)&bias[col];
            float2 v0 = {acc[mt][nt][0] + bv.x, acc[mt][nt][1] + bv.y};
            float2 v1 = {acc[mt][nt][2] + bv.x, acc[mt][nt][3] + bv.y};
            *(float2*)&C[(size_t)row0 * N + col] = v0;
            *(float2*)&C[(size_t)(row0 + 8) * N + col] = v1;
        }
    }
}

__global__ __launch_bounds__(256, 2)
void gemm_val(const float* __restrict__ bias) {
    gemm_body(g_vh, g_vl, gWv_h, gWv_l, bias, g_val, 256,
              blockIdx.x * 128, blockIdx.y * 128);
}

__global__ __launch_bounds__(256, 2)
void gemm_qoa(const float* __restrict__ b_off, const float* __restrict__ b_att) {
    if (blockIdx.y < 2)
        gemm_body(g_qh, g_ql, gWo_h, gWo_l, b_off, g_off, 256,
                  blockIdx.x * 128, blockIdx.y * 128);
    else
        gemm_body(g_qh, g_ql, gWa_h, gWa_l, b_att, g_attn, 128,
                  blockIdx.x * 128, 0);
}

__global__ __launch_bounds__(256, 2)
void gemm_out(const float* __restrict__ bias, float* __restrict__ out) {
    gemm_body(g_sh, g_sl, gWu_h, gWu_l, bias, out, 256,
              blockIdx.x * 128, blockIdx.y * 128);
}

// ---------------------------------------------------------------------------
// Deformable sampler: one warp per (b, q, h); corner-parallel float4 gathers.
// Emits samp directly as bf16 hi/lo planes for the out-GEMM.
// ---------------------------------------------------------------------------
__global__ __launch_bounds__(256)
void sampler(const float* __restrict__ refp) {
    __shared__ __align__(16) float smp[8][16][8];
    const unsigned FULL = 0xffffffffu;
    const int warp = threadIdx.x >> 5;
    const int lane = threadIdx.x & 31;
    const int wid  = blockIdx.x * 8 + warp;

    const int h  = wid & 7;
    const int bq = wid >> 3;
    const int b  = (bq >= NQ) ? 1 : 0;

    float myoff = g_off[(size_t)bq * 256 + h * 32 + lane];
    float logit = (lane < 16) ? g_attn[(size_t)bq * 128 + h * 16 + lane] : -1e30f;
    float myref = (lane < 8)  ? refp[(size_t)bq * 8 + lane] : 0.0f;

    float m = logit;
#pragma unroll
    for (int o = 8; o > 0; o >>= 1) m = fmaxf(m, __shfl_xor_sync(FULL, m, o));
    float e = (lane < 16) ? __expf(logit - m) : 0.0f;
    float s = e;
#pragma unroll
    for (int o = 8; o > 0; o >>= 1) s += __shfl_xor_sync(FULL, s, o);
    float aw = e / s;

    {
        int p = lane & 15;
        int l = p >> 2;
        float ox = __shfl_sync(FULL, myoff, 2 * p);
        float oy = __shfl_sync(FULL, myoff, 2 * p + 1);
        float rx = __shfl_sync(FULL, myref, 2 * l);
        float ry = __shfl_sync(FULL, myref, 2 * l + 1);

        const int Wl = LVL_W[l];
        const int st = LVL_S[l];
        float x = rx * (float)Wl + ox - 0.5f;
        float y = ry * (float)Wl + oy - 0.5f;
        float xf = floorf(x), yf = floorf(y);
        int x0 = (int)xf, y0 = (int)yf;
        float fx = x - xf, fy = y - yf;

        float w00 = (1.0f - fx) * (1.0f - fy) * aw;
        float w10 = fx * (1.0f - fy) * aw;
        float w01 = (1.0f - fx) * fy * aw;
        float w11 = fx * fy * aw;

        bool vx0 = (x0 >= 0) && (x0 < Wl);
        bool vx1 = (x0 + 1 >= 0) && (x0 + 1 < Wl);
        bool vy0 = (y0 >= 0) && (y0 < Wl);
        bool vy1 = (y0 + 1 >= 0) && (y0 + 1 < Wl);
        w00 = (vx0 && vy0) ? w00 : 0.0f;
        w10 = (vx1 && vy0) ? w10 : 0.0f;
        w01 = (vx0 && vy1) ? w01 : 0.0f;
        w11 = (vx1 && vy1) ? w11 : 0.0f;

        int xc0 = min(max(x0, 0), Wl - 1);
        int xc1 = min(max(x0 + 1, 0), Wl - 1);
        int yc0 = min(max(y0, 0), Wl - 1);
        int yc1 = min(max(y0 + 1, 0), Wl - 1);

        int i00 = (st + yc0 * Wl + xc0) << 10;   // byte offsets (x256 floats x4B)
        int i10 = (st + yc0 * Wl + xc1) << 10;
        int i01 = (st + yc1 * Wl + xc0) << 10;
        int i11 = (st + yc1 * Wl + xc1) << 10;

        if (lane < 16) {
            *(float4*)&smp[warp][p][0] =
                make_float4(__int_as_float(i00), w00, __int_as_float(i10), w10);
            *(float4*)&smp[warp][p][4] =
                make_float4(__int_as_float(i01), w01, __int_as_float(i11), w11);
        }
    }
    __syncwarp();

    const int c = lane >> 3;
    const int u = lane & 7;
    const char* vb = (const char*)(g_val + (size_t)b * (NV * 256) + h * 32) + u * 16;

    float4 acc = make_float4(0.0f, 0.0f, 0.0f, 0.0f);
#pragma unroll
    for (int p = 0; p < 16; p++) {
        float2 pr = *(const float2*)&smp[warp][p][2 * c];
        float w = pr.y;
        float4 v = __ldg((const float4*)(vb + __float_as_int(pr.x)));
        acc.x = fmaf(w, v.x, acc.x);
        acc.y = fmaf(w, v.y, acc.y);
        acc.z = fmaf(w, v.z, acc.z);
        acc.w = fmaf(w, v.w, acc.w);
    }
#pragma unroll
    for (int o = 8; o <= 16; o <<= 1) {
        acc.x += __shfl_xor_sync(FULL, acc.x, o);
        acc.y += __shfl_xor_sync(FULL, acc.y, o);
        acc.z += __shfl_xor_sync(FULL, acc.z, o);
        acc.w += __shfl_xor_sync(FULL, acc.w, o);
    }

    if (lane < 8) {
        uint32_t h0,l0,h1,l1;
        split2(acc.x, acc.y, h0, l0);
        split2(acc.z, acc.w, h1, l1);
        size_t o8 = (size_t)bq * 256 + h * 32 + lane * 4;
        *(uint2*)&g_sh[o8] = make_uint2(h0, h1);
        *(uint2*)&g_sl[o8] = make_uint2(l0, l1);
    }
}

// ---------------------------------------------------------------------------
// kernel_launch
// Inputs: 0 query, 1 value, 2 reference_points, 3 spatial_shapes,
// 4 W_off, 5 b_off, 6 W_attn, 7 b_attn, 8 W_v, 9 b_v, 10 W_out, 11 b_out
// ---------------------------------------------------------------------------
extern "C" void kernel_launch(void* const* d_in, const int* in_sizes, int n_in,
                              void* d_out, int out_size) {
    const float* query = (const float*)d_in[0];
    const float* value = (const float*)d_in[1];
    const float* refp  = (const float*)d_in[2];
    const float* W_off = (const float*)d_in[4];
    const float* b_off = (const float*)d_in[5];
    const float* W_att = (const float*)d_in[6];
    const float* b_att = (const float*)d_in[7];
    const float* W_v   = (const float*)d_in[8];
    const float* b_v   = (const float*)d_in[9];
    const float* W_out = (const float*)d_in[10];
    const float* b_out = (const float*)d_in[11];
    float* out = (float*)d_out;

    cudaFuncSetAttribute(gemm_val, cudaFuncAttributeMaxDynamicSharedMemorySize, DSMEM_BYTES);
    cudaFuncSetAttribute(gemm_qoa, cudaFuncAttributeMaxDynamicSharedMemorySize, DSMEM_BYTES);
    cudaFuncSetAttribute(gemm_out, cudaFuncAttributeMaxDynamicSharedMemorySize, DSMEM_BYTES);

    dim3 blk(256);

    convert_acts<<<2 * (ACT_WORDS / 256), blk>>>(query, value);
    convert_wts<<<448, blk>>>(W_v, W_off, W_att, W_out);

    gemm_val<<<dim3(MROWS / 128, 2), blk, DSMEM_BYTES>>>(b_v);
    gemm_qoa<<<dim3(MROWS / 128, 3), blk, DSMEM_BYTES>>>(b_off, b_att);
    sampler<<<MROWS, blk>>>(refp);
    gemm_out<<<dim3(MROWS / 128, 2), blk, DSMEM_BYTES>>>(b_out, out);
}

// round 10
// speedup vs baseline: 1.3390x; 1.0117x over previous
#include <cuda_runtime.h>
#include <cuda_bf16.h>
#include <math.h>
#include <stdint.h>

// Problem constants (fixed by the reference)
#define BS 2
#define NQ 21760
#define NV 21760
#define MROWS (BS * NQ)   // 43520
#define CHUNK 16          // consecutive queries per sampler block

__device__ __constant__ int LVL_W[4] = {128, 64, 32, 16};
__device__ __constant__ int LVL_S[4] = {0, 16384, 20480, 21504};

// ---------------- scratch (allocation-free rule: __device__ globals) --------
__device__ float g_val [MROWS * 256];
__device__ float g_off [MROWS * 256];
__device__ float g_attn[MROWS * 128];

// bf16 hi/lo planes for GEMM A operands
__device__ __align__(16) __nv_bfloat16 g_qh[MROWS * 256], g_ql[MROWS * 256];
__device__ __align__(16) __nv_bfloat16 g_vh[MROWS * 256], g_vl[MROWS * 256];
__device__ __align__(16) __nv_bfloat16 g_sh[MROWS * 256], g_sl[MROWS * 256];

// k-pair-packed bf16 weight planes: word[kp*N+n] = (bf16 W[2kp+1][n] <<16) | bf16 W[2kp][n]
__device__ __align__(16) uint32_t gWv_h[128 * 256], gWv_l[128 * 256];
__device__ __align__(16) uint32_t gWo_h[128 * 256], gWo_l[128 * 256];
__device__ __align__(16) uint32_t gWa_h[128 * 128], gWa_l[128 * 128];
__device__ __align__(16) uint32_t gWu_h[128 * 256], gWu_l[128 * 256];

// ---------------------------------------------------------------------------
__device__ __forceinline__ void split2(float x, float y, uint32_t &hi, uint32_t &lo) {
    __nv_bfloat16 hx = __float2bfloat16_rn(x);
    __nv_bfloat16 hy = __float2bfloat16_rn(y);
    __nv_bfloat16 lx = __float2bfloat16_rn(x - __bfloat162float(hx));
    __nv_bfloat16 ly = __float2bfloat16_rn(y - __bfloat162float(hy));
    hi = ((uint32_t)__bfloat16_as_ushort(hy) << 16) | (uint32_t)__bfloat16_as_ushort(hx);
    lo = ((uint32_t)__bfloat16_as_ushort(ly) << 16) | (uint32_t)__bfloat16_as_ushort(lx);
}

__device__ __forceinline__ void mma_bf16(float *d, const uint32_t *a, const uint32_t *b) {
    asm volatile(
        "mma.sync.aligned.m16n8k16.row.col.f32.bf16.bf16.f32 "
        "{%0,%1,%2,%3}, {%4,%5,%6,%7}, {%8,%9}, {%0,%1,%2,%3};\n"
        : "+f"(d[0]), "+f"(d[1]), "+f"(d[2]), "+f"(d[3])
        : "r"(a[0]), "r"(a[1]), "r"(a[2]), "r"(a[3]), "r"(b[0]), "r"(b[1]));
}

__device__ __forceinline__ void ldsm4(uint32_t *r, uint32_t addr) {
    asm volatile("ldmatrix.sync.aligned.m8n8.x4.shared.b16 {%0,%1,%2,%3}, [%4];"
                 : "=r"(r[0]), "=r"(r[1]), "=r"(r[2]), "=r"(r[3]) : "r"(addr));
}

__device__ __forceinline__ void cp16(uint32_t dst, const void* src) {
    asm volatile("cp.async.cg.shared.global [%0], [%1], 16;\n" :: "r"(dst), "l"(src));
}
__device__ __forceinline__ void cp_commit() { asm volatile("cp.async.commit_group;\n"); }
__device__ __forceinline__ void cp_wait1() { asm volatile("cp.async.wait_group 1;\n"); }
__device__ __forceinline__ void cp_wait0() { asm volatile("cp.async.wait_group 0;\n"); }

// ---------------------------------------------------------------------------
// Conversion kernels
// ---------------------------------------------------------------------------
#define ACT_WORDS (MROWS * 256 / 8)

__global__ __launch_bounds__(256)
void convert_acts(const float* __restrict__ query, const float* __restrict__ value) {
    int idx = blockIdx.x * 256 + threadIdx.x;
    const float* src; __nv_bfloat16 *H, *L;
    if (idx < ACT_WORDS) { src = query; H = g_qh; L = g_ql; }
    else { idx -= ACT_WORDS; src = value; H = g_vh; L = g_vl; }
    float4 f0 = *(const float4*)&src[idx * 8];
    float4 f1 = *(const float4*)&src[idx * 8 + 4];
    uint32_t h0,l0,h1,l1,h2,l2,h3,l3;
    split2(f0.x, f0.y, h0, l0);
    split2(f0.z, f0.w, h1, l1);
    split2(f1.x, f1.y, h2, l2);
    split2(f1.z, f1.w, h3, l3);
    *(uint4*)&H[idx * 8] = make_uint4(h0, h1, h2, h3);
    *(uint4*)&L[idx * 8] = make_uint4(l0, l1, l2, l3);
}

__global__ __launch_bounds__(256)
void convert_wts(const float* __restrict__ Wv, const float* __restrict__ Wo,
                 const float* __restrict__ Wa, const float* __restrict__ Wu) {
    int idx = blockIdx.x * 256 + threadIdx.x;
    const float* W; uint32_t *H, *L; int N;
    if (idx < 32768)      { W = Wv; H = gWv_h; L = gWv_l; N = 256; }
    else if (idx < 65536) { idx -= 32768; W = Wo; H = gWo_h; L = gWo_l; N = 256; }
    else if (idx < 81920) { idx -= 65536; W = Wa; H = gWa_h; L = gWa_l; N = 128; }
    else                  { idx -= 81920; W = Wu; H = gWu_h; L = gWu_l; N = 256; }
    int kp = idx / N, n = idx - kp * N;
    float e = W[(2 * kp) * N + n];
    float o = W[(2 * kp + 1) * N + n];
    uint32_t hi, lo;
    split2(e, o, hi, lo);
    H[kp * N + n] = hi;
    L[kp * N + n] = lo;
}

// ---------------------------------------------------------------------------
// GEMM: C[M,N] = A @ B + bias from pre-split bf16 planes.
// Tile 128x128, BK=16, 256 thr (8 warps, warp tile 64x32).
// 3-stage cp.async pipeline (dynamic smem), ldmatrix A frags, scalar LDS B.
// 3-pass split MMA (hh + hl + lh), pass-major inner order for acc independence.
// ---------------------------------------------------------------------------
#define A_BUF_B 6144
#define B_BUF_B 4352
#define OFF_AL 18432
#define OFF_BH 36864
#define OFF_BL 49920
#define DSMEM_BYTES 62976

__device__ __forceinline__ void gemm_body(
    const __nv_bfloat16* __restrict__ Agh, const __nv_bfloat16* __restrict__ Agl,
    const uint32_t* __restrict__ Bgh, const uint32_t* __restrict__ Bgl,
    const float* __restrict__ bias, float* __restrict__ C,
    int N, int bm, int bn)
{
    extern __shared__ __align__(128) char dsm[];
    const uint32_t sbase = (uint32_t)__cvta_generic_to_shared(dsm);

    const int tid  = threadIdx.x;
    const int lane = tid & 31;
    const int warp = tid >> 5;
    const int g = lane >> 2;
    const int t = lane & 3;
    const int warp_m = (warp >> 2) * 64;
    const int warp_n = (warp & 3) * 32;

    const int arow  = tid >> 1;
    const int ahalf = tid & 1;
    const int brow  = tid >> 5;
    const int bc    = tid & 31;

    const uint32_t aDst = arow * 48 + ahalf * 16;
    const uint32_t bDst = brow * 544 + bc * 16;
    const __nv_bfloat16* aSrcH = Agh + (size_t)(bm + arow) * 256 + ahalf * 8;
    const __nv_bfloat16* aSrcL = Agl + (size_t)(bm + arow) * 256 + ahalf * 8;
    const uint32_t* bSrcH = Bgh + (size_t)brow * N + bn + bc * 4;
    const uint32_t* bSrcL = Bgl + (size_t)brow * N + bn + bc * 4;

    const int lr = (lane & 7) + ((lane >> 3) & 1) * 8;
    const int lb = (lane >> 4) * 16;
    const uint32_t aFrag = (warp_m + lr) * 48 + lb;

    float acc[4][4][4];
#pragma unroll
    for (int i = 0; i < 4; i++)
#pragma unroll
        for (int j = 0; j < 4; j++)
#pragma unroll
            for (int r = 0; r < 4; r++) acc[i][j][r] = 0.0f;

    auto load_chunk = [&](int stage, int buf) {
        cp16(sbase + buf * A_BUF_B + aDst, aSrcH + stage * 16);
        cp16(sbase + OFF_AL + buf * A_BUF_B + aDst, aSrcL + stage * 16);
        cp16(sbase + OFF_BH + buf * B_BUF_B + bDst, bSrcH + (size_t)stage * 8 * N);
        cp16(sbase + OFF_BL + buf * B_BUF_B + bDst, bSrcL + (size_t)stage * 8 * N);
        cp_commit();
    };

    load_chunk(0, 0);
    load_chunk(1, 1);

#pragma unroll
    for (int it = 0; it < 16; it++) {
        const int buf = it % 3;
        if (it < 15) cp_wait1(); else cp_wait0();
        __syncthreads();
        if (it < 14) load_chunk(it + 2, (it + 2) % 3);

        const uint32_t* BhW = (const uint32_t*)(dsm + OFF_BH + buf * B_BUF_B);
        const uint32_t* BlW = (const uint32_t*)(dsm + OFF_BL + buf * B_BUF_B);
        uint32_t bfh[4][2], bfl[4][2];
#pragma unroll
        for (int nt = 0; nt < 4; nt++) {
            int cb = warp_n + nt * 8 + g;
            bfh[nt][0] = BhW[t * 136 + cb];
            bfh[nt][1] = BhW[(t + 4) * 136 + cb];
            bfl[nt][0] = BlW[t * 136 + cb];
            bfl[nt][1] = BlW[(t + 4) * 136 + cb];
        }
        // per-mt: 2 ldmatrix + pass-major MMAs (4 independent per pass)
#pragma unroll
        for (int mt = 0; mt < 4; mt++) {
            uint32_t ah[4], al[4];
            ldsm4(ah, sbase + buf * A_BUF_B + aFrag + mt * 768);
            ldsm4(al, sbase + OFF_AL + buf * A_BUF_B + aFrag + mt * 768);
#pragma unroll
            for (int nt = 0; nt < 4; nt++) mma_bf16(acc[mt][nt], al, bfh[nt]);
#pragma unroll
            for (int nt = 0; nt < 4; nt++) mma_bf16(acc[mt][nt], ah, bfl[nt]);
#pragma unroll
            for (int nt = 0; nt < 4; nt++) mma_bf16(acc[mt][nt], ah, bfh[nt]);
        }
    }

    // epilogue
#pragma unroll
    for (int mt = 0; mt < 4; mt++) {
        int row0 = bm + warp_m + mt * 16 + g;
#pragma unroll
        for (int nt = 0; nt < 4; nt++) {
            int col = bn + warp_n + nt * 8 + 2 * t;
            float2 bv = *(const float2*)&bias[col];
            float2 v0 = {acc[mt][nt][0] + bv.x, acc[mt][nt][1] + bv.y};
            float2 v1 = {acc[mt][nt][2] + bv.x, acc[mt][nt][3] + bv.y};
            *(float2*)&C[(size_t)row0 * N + col] = v0;
            *(float2*)&C[(size_t)(row0 + 8) * N + col] = v1;
        }
    }
}

__global__ __launch_bounds__(256, 2)
void gemm_val(const float* __restrict__ bias) {
    gemm_body(g_vh, g_vl, gWv_h, gWv_l, bias, g_val, 256,
              blockIdx.x * 128, blockIdx.y * 128);
}

__global__ __launch_bounds__(256, 2)
void gemm_qoa(const float* __restrict__ b_off, const float* __restrict__ b_att) {
    if (blockIdx.y < 2)
        gemm_body(g_qh, g_ql, gWo_h, gWo_l, b_off, g_off, 256,
                  blockIdx.x * 128, blockIdx.y * 128);
    else
        gemm_body(g_qh, g_ql, gWa_h, gWa_l, b_att, g_attn, 128,
                  blockIdx.x * 128, 0);
}

__global__ __launch_bounds__(256, 2)
void gemm_out(const float* __restrict__ bias, float* __restrict__ out) {
    gemm_body(g_sh, g_sl, gWu_h, gWu_l, bias, out, 256,
              blockIdx.x * 128, blockIdx.y * 128);
}

// ---------------------------------------------------------------------------
// Deformable sampler: block = 8 warps = 8 heads, processing CHUNK consecutive
// queries (spatially adjacent -> corner cache-line reuse in L1/L2).
// Per query: softmax + per-point precompute on lanes 0..15, then
// corner-parallel float4 gathers (lane = corner*8 + chan-group).
// Next query's inputs prefetched before the gather loop.
// ---------------------------------------------------------------------------
__global__ __launch_bounds__(256)
void sampler(const float* __restrict__ refp) {
    __shared__ __align__(16) float smp[8][16][8];
    const unsigned FULL = 0xffffffffu;
    const int h    = threadIdx.x >> 5;   // warp == head
    const int lane = threadIdx.x & 31;
    const int base = blockIdx.x * CHUNK;
    const int b    = (base >= NQ) ? 1 : 0;   // chunks never straddle batches

    const int c = lane >> 3;
    const int u = lane & 7;
    const char* vb = (const char*)(g_val + (size_t)b * (NV * 256) + h * 32) + u * 16;

    // preload query 0
    float myoff = g_off[(size_t)base * 256 + h * 32 + lane];
    float logit = (lane < 16) ? g_attn[(size_t)base * 128 + h * 16 + lane] : -1e30f;
    float myref = (lane < 8)  ? refp[(size_t)base * 8 + lane] : 0.0f;

    for (int i = 0; i < CHUNK; i++) {
        const int bq = base + i;

        // softmax over 16 logits
        float m = logit;
#pragma unroll
        for (int o = 8; o > 0; o >>= 1) m = fmaxf(m, __shfl_xor_sync(FULL, m, o));
        float e = (lane < 16) ? __expf(logit - m) : 0.0f;
        float s = e;
#pragma unroll
        for (int o = 8; o > 0; o >>= 1) s += __shfl_xor_sync(FULL, s, o);
        float aw = e / s;

        // per-point precompute on lanes 0..15
        {
            int p = lane & 15;
            int l = p >> 2;
            float ox = __shfl_sync(FULL, myoff, 2 * p);
            float oy = __shfl_sync(FULL, myoff, 2 * p + 1);
            float rx = __shfl_sync(FULL, myref, 2 * l);
            float ry = __shfl_sync(FULL, myref, 2 * l + 1);

            const int Wl = LVL_W[l];
            const int st = LVL_S[l];
            float x = rx * (float)Wl + ox - 0.5f;
            float y = ry * (float)Wl + oy - 0.5f;
            float xf = floorf(x), yf = floorf(y);
            int x0 = (int)xf, y0 = (int)yf;
            float fx = x - xf, fy = y - yf;

            float w00 = (1.0f - fx) * (1.0f - fy) * aw;
            float w10 = fx * (1.0f - fy) * aw;
            float w01 = (1.0f - fx) * fy * aw;
            float w11 = fx * fy * aw;

            bool vx0 = (x0 >= 0) && (x0 < Wl);
            bool vx1 = (x0 + 1 >= 0) && (x0 + 1 < Wl);
            bool vy0 = (y0 >= 0) && (y0 < Wl);
            bool vy1 = (y0 + 1 >= 0) && (y0 + 1 < Wl);
            w00 = (vx0 && vy0) ? w00 : 0.0f;
            w10 = (vx1 && vy0) ? w10 : 0.0f;
            w01 = (vx0 && vy1) ? w01 : 0.0f;
            w11 = (vx1 && vy1) ? w11 : 0.0f;

            int xc0 = min(max(x0, 0), Wl - 1);
            int xc1 = min(max(x0 + 1, 0), Wl - 1);
            int yc0 = min(max(y0, 0), Wl - 1);
            int yc1 = min(max(y0 + 1, 0), Wl - 1);

            int i00 = (st + yc0 * Wl + xc0) << 10;   // byte offsets
            int i10 = (st + yc0 * Wl + xc1) << 10;
            int i01 = (st + yc1 * Wl + xc0) << 10;
            int i11 = (st + yc1 * Wl + xc1) << 10;

            if (lane < 16) {
                *(float4*)&smp[h][p][0] =
                    make_float4(__int_as_float(i00), w00, __int_as_float(i10), w10);
                *(float4*)&smp[h][p][4] =
                    make_float4(__int_as_float(i01), w01, __int_as_float(i11), w11);
            }
        }

        // prefetch next query's inputs (hides L2 latency behind the gathers)
        if (i + 1 < CHUNK) {
            const int nq = bq + 1;
            myoff = g_off[(size_t)nq * 256 + h * 32 + lane];
            logit = (lane < 16) ? g_attn[(size_t)nq * 128 + h * 16 + lane] : -1e30f;
            myref = (lane < 8)  ? refp[(size_t)nq * 8 + lane] : 0.0f;
        }
        __syncwarp();

        float4 acc = make_float4(0.0f, 0.0f, 0.0f, 0.0f);
#pragma unroll
        for (int p = 0; p < 16; p++) {
            float2 pr = *(const float2*)&smp[h][p][2 * c];
            float w = pr.y;
            float4 v = __ldg((const float4*)(vb + __float_as_int(pr.x)));
            acc.x = fmaf(w, v.x, acc.x);
            acc.y = fmaf(w, v.y, acc.y);
            acc.z = fmaf(w, v.z, acc.z);
            acc.w = fmaf(w, v.w, acc.w);
        }
#pragma unroll
        for (int o = 8; o <= 16; o <<= 1) {
            acc.x += __shfl_xor_sync(FULL, acc.x, o);
            acc.y += __shfl_xor_sync(FULL, acc.y, o);
            acc.z += __shfl_xor_sync(FULL, acc.z, o);
            acc.w += __shfl_xor_sync(FULL, acc.w, o);
        }

        if (lane < 8) {
            uint32_t h0,l0,h1,l1;
            split2(acc.x, acc.y, h0, l0);
            split2(acc.z, acc.w, h1, l1);
            size_t o8 = (size_t)bq * 256 + h * 32 + lane * 4;
            *(uint2*)&g_sh[o8] = make_uint2(h0, h1);
            *(uint2*)&g_sl[o8] = make_uint2(l0, l1);
        }
        __syncwarp();   // guard smp reuse across iterations
    }
}

// ---------------------------------------------------------------------------
// kernel_launch
// Inputs: 0 query, 1 value, 2 reference_points, 3 spatial_shapes,
// 4 W_off, 5 b_off, 6 W_attn, 7 b_attn, 8 W_v, 9 b_v, 10 W_out, 11 b_out
// ---------------------------------------------------------------------------
extern "C" void kernel_launch(void* const* d_in, const int* in_sizes, int n_in,
                              void* d_out, int out_size) {
    const float* query = (const float*)d_in[0];
    const float* value = (const float*)d_in[1];
    const float* refp  = (const float*)d_in[2];
    const float* W_off = (const float*)d_in[4];
    const float* b_off = (const float*)d_in[5];
    const float* W_att = (const float*)d_in[6];
    const float* b_att = (const float*)d_in[7];
    const float* W_v   = (const float*)d_in[8];
    const float* b_v   = (const float*)d_in[9];
    const float* W_out = (const float*)d_in[10];
    const float* b_out = (const float*)d_in[11];
    float* out = (float*)d_out;

    cudaFuncSetAttribute(gemm_val, cudaFuncAttributeMaxDynamicSharedMemorySize, DSMEM_BYTES);
    cudaFuncSetAttribute(gemm_qoa, cudaFuncAttributeMaxDynamicSharedMemorySize, DSMEM_BYTES);
    cudaFuncSetAttribute(gemm_out, cudaFuncAttributeMaxDynamicSharedMemorySize, DSMEM_BYTES);

    dim3 blk(256);

    convert_acts<<<2 * (ACT_WORDS / 256), blk>>>(query, value);
    convert_wts<<<448, blk>>>(W_v, W_off, W_att, W_out);

    gemm_val<<<dim3(MROWS / 128, 2), blk, DSMEM_BYTES>>>(b_v);
    gemm_qoa<<<dim3(MROWS / 128, 3), blk, DSMEM_BYTES>>>(b_off, b_att);
    sampler<<<MROWS / CHUNK, blk>>>(refp);
    gemm_out<<<dim3(MROWS / 128, 2), blk, DSMEM_BYTES>>>(b_out, out);
}

// round 11
// speedup vs baseline: 1.3655x; 1.0198x over previous
#include <cuda_runtime.h>
#include <cuda_bf16.h>
#include <cuda_fp16.h>
#include <math.h>
#include <stdint.h>

// Problem constants (fixed by the reference)
#define BS 2
#define NQ 21760
#define NV 21760
#define MROWS (BS * NQ)   // 43520
#define CHUNK 16          // consecutive queries per sampler block

__device__ __constant__ int LVL_W[4] = {128, 64, 32, 16};
__device__ __constant__ int LVL_S[4] = {0, 16384, 20480, 21504};

// ---------------- scratch (allocation-free rule: __device__ globals) --------
__device__ __align__(16) __half g_val [MROWS * 256];   // value @ W_v + b_v (fp16)
__device__ float g_off [MROWS * 256];
__device__ float g_attn[MROWS * 128];

// bf16 hi/lo planes for GEMM A operands
__device__ __align__(16) __nv_bfloat16 g_qh[MROWS * 256], g_ql[MROWS * 256];
__device__ __align__(16) __nv_bfloat16 g_vh[MROWS * 256], g_vl[MROWS * 256];
__device__ __align__(16) __nv_bfloat16 g_sh[MROWS * 256], g_sl[MROWS * 256];

// k-pair-packed bf16 weight planes: word[kp*N+n] = (bf16 W[2kp+1][n] <<16) | bf16 W[2kp][n]
__device__ __align__(16) uint32_t gWv_h[128 * 256], gWv_l[128 * 256];
__device__ __align__(16) uint32_t gWo_h[128 * 256], gWo_l[128 * 256];
__device__ __align__(16) uint32_t gWa_h[128 * 128], gWa_l[128 * 128];
__device__ __align__(16) uint32_t gWu_h[128 * 256], gWu_l[128 * 256];

// ---------------------------------------------------------------------------
__device__ __forceinline__ void split2(float x, float y, uint32_t &hi, uint32_t &lo) {
    __nv_bfloat16 hx = __float2bfloat16_rn(x);
    __nv_bfloat16 hy = __float2bfloat16_rn(y);
    __nv_bfloat16 lx = __float2bfloat16_rn(x - __bfloat162float(hx));
    __nv_bfloat16 ly = __float2bfloat16_rn(y - __bfloat162float(hy));
    hi = ((uint32_t)__bfloat16_as_ushort(hy) << 16) | (uint32_t)__bfloat16_as_ushort(hx);
    lo = ((uint32_t)__bfloat16_as_ushort(ly) << 16) | (uint32_t)__bfloat16_as_ushort(lx);
}

__device__ __forceinline__ void mma_bf16(float *d, const uint32_t *a, const uint32_t *b) {
    asm volatile(
        "mma.sync.aligned.m16n8k16.row.col.f32.bf16.bf16.f32 "
        "{%0,%1,%2,%3}, {%4,%5,%6,%7}, {%8,%9}, {%0,%1,%2,%3};\n"
        : "+f"(d[0]), "+f"(d[1]), "+f"(d[2]), "+f"(d[3])
        : "r"(a[0]), "r"(a[1]), "r"(a[2]), "r"(a[3]), "r"(b[0]), "r"(b[1]));
}

__device__ __forceinline__ void ldsm4(uint32_t *r, uint32_t addr) {
    asm volatile("ldmatrix.sync.aligned.m8n8.x4.shared.b16 {%0,%1,%2,%3}, [%4];"
                 : "=r"(r[0]), "=r"(r[1]), "=r"(r[2]), "=r"(r[3]) : "r"(addr));
}

__device__ __forceinline__ void cp16(uint32_t dst, const void* src) {
    asm volatile("cp.async.cg.shared.global [%0], [%1], 16;\n" :: "r"(dst), "l"(src));
}
__device__ __forceinline__ void cp_commit() { asm volatile("cp.async.commit_group;\n"); }
__device__ __forceinline__ void cp_wait1() { asm volatile("cp.async.wait_group 1;\n"); }
__device__ __forceinline__ void cp_wait0() { asm volatile("cp.async.wait_group 0;\n"); }

// ---------------------------------------------------------------------------
// Conversion kernels
// ---------------------------------------------------------------------------
#define ACT_WORDS (MROWS * 256 / 8)

__global__ __launch_bounds__(256)
void convert_acts(const float* __restrict__ query, const float* __restrict__ value) {
    int idx = blockIdx.x * 256 + threadIdx.x;
    const float* src; __nv_bfloat16 *H, *L;
    if (idx < ACT_WORDS) { src = query; H = g_qh; L = g_ql; }
    else { idx -= ACT_WORDS; src = value; H = g_vh; L = g_vl; }
    float4 f0 = *(const float4*)&src[idx * 8];
    float4 f1 = *(const float4*)&src[idx * 8 + 4];
    uint32_t h0,l0,h1,l1,h2,l2,h3,l3;
    split2(f0.x, f0.y, h0, l0);
    split2(f0.z, f0.w, h1, l1);
    split2(f1.x, f1.y, h2, l2);
    split2(f1.z, f1.w, h3, l3);
    *(uint4*)&H[idx * 8] = make_uint4(h0, h1, h2, h3);
    *(uint4*)&L[idx * 8] = make_uint4(l0, l1, l2, l3);
}

__global__ __launch_bounds__(256)
void convert_wts(const float* __restrict__ Wv, const float* __restrict__ Wo,
                 const float* __restrict__ Wa, const float* __restrict__ Wu) {
    int idx = blockIdx.x * 256 + threadIdx.x;
    const float* W; uint32_t *H, *L; int N;
    if (idx < 32768)      { W = Wv; H = gWv_h; L = gWv_l; N = 256; }
    else if (idx < 65536) { idx -= 32768; W = Wo; H = gWo_h; L = gWo_l; N = 256; }
    else if (idx < 81920) { idx -= 65536; W = Wa; H = gWa_h; L = gWa_l; N = 128; }
    else                  { idx -= 81920; W = Wu; H = gWu_h; L = gWu_l; N = 256; }
    int kp = idx / N, n = idx - kp * N;
    float e = W[(2 * kp) * N + n];
    float o = W[(2 * kp + 1) * N + n];
    uint32_t hi, lo;
    split2(e, o, hi, lo);
    H[kp * N + n] = hi;
    L[kp * N + n] = lo;
}

// ---------------------------------------------------------------------------
// GEMM: C[M,N] = A @ B + bias from pre-split bf16 planes.
// Tile 128x128, BK=16, 256 thr (8 warps, warp tile 64x32).
// 3-stage cp.async pipeline (dynamic smem), ldmatrix A frags, scalar LDS B.
// 3-pass split MMA (hh + hl + lh). Output fp32 or fp16 (template).
// ---------------------------------------------------------------------------
#define A_BUF_B 6144
#define B_BUF_B 4352
#define OFF_AL 18432
#define OFF_BH 36864
#define OFF_BL 49920
#define DSMEM_BYTES 62976

template <bool HALF_OUT>
__device__ __forceinline__ void gemm_body(
    const __nv_bfloat16* __restrict__ Agh, const __nv_bfloat16* __restrict__ Agl,
    const uint32_t* __restrict__ Bgh, const uint32_t* __restrict__ Bgl,
    const float* __restrict__ bias, void* __restrict__ Cp,
    int N, int bm, int bn)
{
    extern __shared__ __align__(128) char dsm[];
    const uint32_t sbase = (uint32_t)__cvta_generic_to_shared(dsm);

    const int tid  = threadIdx.x;
    const int lane = tid & 31;
    const int warp = tid >> 5;
    const int g = lane >> 2;
    const int t = lane & 3;
    const int warp_m = (warp >> 2) * 64;
    const int warp_n = (warp & 3) * 32;

    const int arow  = tid >> 1;
    const int ahalf = tid & 1;
    const int brow  = tid >> 5;
    const int bc    = tid & 31;

    const uint32_t aDst = arow * 48 + ahalf * 16;
    const uint32_t bDst = brow * 544 + bc * 16;
    const __nv_bfloat16* aSrcH = Agh + (size_t)(bm + arow) * 256 + ahalf * 8;
    const __nv_bfloat16* aSrcL = Agl + (size_t)(bm + arow) * 256 + ahalf * 8;
    const uint32_t* bSrcH = Bgh + (size_t)brow * N + bn + bc * 4;
    const uint32_t* bSrcL = Bgl + (size_t)brow * N + bn + bc * 4;

    const int lr = (lane & 7) + ((lane >> 3) & 1) * 8;
    const int lb = (lane >> 4) * 16;
    const uint32_t aFrag = (warp_m + lr) * 48 + lb;

    float acc[4][4][4];
#pragma unroll
    for (int i = 0; i < 4; i++)
#pragma unroll
        for (int j = 0; j < 4; j++)
#pragma unroll
            for (int r = 0; r < 4; r++) acc[i][j][r] = 0.0f;

    auto load_chunk = [&](int stage, int buf) {
        cp16(sbase + buf * A_BUF_B + aDst, aSrcH + stage * 16);
        cp16(sbase + OFF_AL + buf * A_BUF_B + aDst, aSrcL + stage * 16);
        cp16(sbase + OFF_BH + buf * B_BUF_B + bDst, bSrcH + (size_t)stage * 8 * N);
        cp16(sbase + OFF_BL + buf * B_BUF_B + bDst, bSrcL + (size_t)stage * 8 * N);
        cp_commit();
    };

    load_chunk(0, 0);
    load_chunk(1, 1);

#pragma unroll
    for (int it = 0; it < 16; it++) {
        const int buf = it % 3;
        if (it < 15) cp_wait1(); else cp_wait0();
        __syncthreads();
        if (it < 14) load_chunk(it + 2, (it + 2) % 3);

        const uint32_t* BhW = (const uint32_t*)(dsm + OFF_BH + buf * B_BUF_B);
        const uint32_t* BlW = (const uint32_t*)(dsm + OFF_BL + buf * B_BUF_B);
        uint32_t bfh[4][2], bfl[4][2];
#pragma unroll
        for (int nt = 0; nt < 4; nt++) {
            int cb = warp_n + nt * 8 + g;
            bfh[nt][0] = BhW[t * 136 + cb];
            bfh[nt][1] = BhW[(t + 4) * 136 + cb];
            bfl[nt][0] = BlW[t * 136 + cb];
            bfl[nt][1] = BlW[(t + 4) * 136 + cb];
        }
#pragma unroll
        for (int mt = 0; mt < 4; mt++) {
            uint32_t ah[4], al[4];
            ldsm4(ah, sbase + buf * A_BUF_B + aFrag + mt * 768);
            ldsm4(al, sbase + OFF_AL + buf * A_BUF_B + aFrag + mt * 768);
#pragma unroll
            for (int nt = 0; nt < 4; nt++) mma_bf16(acc[mt][nt], al, bfh[nt]);
#pragma unroll
            for (int nt = 0; nt < 4; nt++) mma_bf16(acc[mt][nt], ah, bfl[nt]);
#pragma unroll
            for (int nt = 0; nt < 4; nt++) mma_bf16(acc[mt][nt], ah, bfh[nt]);
        }
    }

    // epilogue
#pragma unroll
    for (int mt = 0; mt < 4; mt++) {
        int row0 = bm + warp_m + mt * 16 + g;
#pragma unroll
        for (int nt = 0; nt < 4; nt++) {
            int col = bn + warp_n + nt * 8 + 2 * t;
            float2 bv = *(const float2*)&bias[col];
            float vx0 = acc[mt][nt][0] + bv.x, vy0 = acc[mt][nt][1] + bv.y;
            float vx1 = acc[mt][nt][2] + bv.x, vy1 = acc[mt][nt][3] + bv.y;
            if (HALF_OUT) {
                __half* C = (__half*)Cp;
                *(__half2*)&C[(size_t)row0 * N + col] = __floats2half2_rn(vx0, vy0);
                *(__half2*)&C[(size_t)(row0 + 8) * N + col] = __floats2half2_rn(vx1, vy1);
            } else {
                float* C = (float*)Cp;
                *(float2*)&C[(size_t)row0 * N + col] = make_float2(vx0, vy0);
                *(float2*)&C[(size_t)(row0 + 8) * N + col] = make_float2(vx1, vy1);
            }
        }
    }
}

__global__ __launch_bounds__(256, 2)
void gemm_val(const float* __restrict__ bias) {
    gemm_body<true>(g_vh, g_vl, gWv_h, gWv_l, bias, g_val, 256,
                    blockIdx.x * 128, blockIdx.y * 128);
}

__global__ __launch_bounds__(256, 2)
void gemm_qoa(const float* __restrict__ b_off, const float* __restrict__ b_att) {
    if (blockIdx.y < 2)
        gemm_body<false>(g_qh, g_ql, gWo_h, gWo_l, b_off, g_off, 256,
                         blockIdx.x * 128, blockIdx.y * 128);
    else
        gemm_body<false>(g_qh, g_ql, gWa_h, gWa_l, b_att, g_attn, 128,
                         blockIdx.x * 128, 0);
}

__global__ __launch_bounds__(256, 2)
void gemm_out(const float* __restrict__ bias, float* __restrict__ out) {
    gemm_body<false>(g_sh, g_sl, gWu_h, gWu_l, bias, out, 256,
                     blockIdx.x * 128, blockIdx.y * 128);
}

// ---------------------------------------------------------------------------
// Deformable sampler: block = 8 warps = 8 heads, CHUNK consecutive queries.
// Value tensor is fp16: corner slice = 64B; lane = (corner, chan-group of 4),
// each lane gathers uint2 (4 halves), unpacks to fp32, FMAs.
// ---------------------------------------------------------------------------
__global__ __launch_bounds__(256)
void sampler(const float* __restrict__ refp) {
    __shared__ __align__(16) float smp[8][16][8];
    const unsigned FULL = 0xffffffffu;
    const int h    = threadIdx.x >> 5;   // warp == head
    const int lane = threadIdx.x & 31;
    const int base = blockIdx.x * CHUNK;
    const int b    = (base >= NQ) ? 1 : 0;

    const int c = lane >> 3;
    const int u = lane & 7;
    const char* vb = (const char*)(g_val + (size_t)b * (NV * 256) + h * 32) + u * 8;

    // preload query 0
    float myoff = g_off[(size_t)base * 256 + h * 32 + lane];
    float logit = (lane < 16) ? g_attn[(size_t)base * 128 + h * 16 + lane] : -1e30f;
    float myref = (lane < 8)  ? refp[(size_t)base * 8 + lane] : 0.0f;

    for (int i = 0; i < CHUNK; i++) {
        const int bq = base + i;

        // softmax over 16 logits
        float m = logit;
#pragma unroll
        for (int o = 8; o > 0; o >>= 1) m = fmaxf(m, __shfl_xor_sync(FULL, m, o));
        float e = (lane < 16) ? __expf(logit - m) : 0.0f;
        float s = e;
#pragma unroll
        for (int o = 8; o > 0; o >>= 1) s += __shfl_xor_sync(FULL, s, o);
        float aw = e / s;

        // per-point precompute on lanes 0..15
        {
            int p = lane & 15;
            int l = p >> 2;
            float ox = __shfl_sync(FULL, myoff, 2 * p);
            float oy = __shfl_sync(FULL, myoff, 2 * p + 1);
            float rx = __shfl_sync(FULL, myref, 2 * l);
            float ry = __shfl_sync(FULL, myref, 2 * l + 1);

            const int Wl = LVL_W[l];
            const int st = LVL_S[l];
            float x = rx * (float)Wl + ox - 0.5f;
            float y = ry * (float)Wl + oy - 0.5f;
            float xf = floorf(x), yf = floorf(y);
            int x0 = (int)xf, y0 = (int)yf;
            float fx = x - xf, fy = y - yf;

            float w00 = (1.0f - fx) * (1.0f - fy) * aw;
            float w10 = fx * (1.0f - fy) * aw;
            float w01 = (1.0f - fx) * fy * aw;
            float w11 = fx * fy * aw;

            bool vx0 = (x0 >= 0) && (x0 < Wl);
            bool vx1 = (x0 + 1 >= 0) && (x0 + 1 < Wl);
            bool vy0 = (y0 >= 0) && (y0 < Wl);
            bool vy1 = (y0 + 1 >= 0) && (y0 + 1 < Wl);
            w00 = (vx0 && vy0) ? w00 : 0.0f;
            w10 = (vx1 && vy0) ? w10 : 0.0f;
            w01 = (vx0 && vy1) ? w01 : 0.0f;
            w11 = (vx1 && vy1) ? w11 : 0.0f;

            int xc0 = min(max(x0, 0), Wl - 1);
            int xc1 = min(max(x0 + 1, 0), Wl - 1);
            int yc0 = min(max(y0, 0), Wl - 1);
            int yc1 = min(max(y0 + 1, 0), Wl - 1);

            // byte offsets: element idx * 256 halves * 2B = << 9
            int i00 = (st + yc0 * Wl + xc0) << 9;
            int i10 = (st + yc0 * Wl + xc1) << 9;
            int i01 = (st + yc1 * Wl + xc0) << 9;
            int i11 = (st + yc1 * Wl + xc1) << 9;

            if (lane < 16) {
                *(float4*)&smp[h][p][0] =
                    make_float4(__int_as_float(i00), w00, __int_as_float(i10), w10);
                *(float4*)&smp[h][p][4] =
                    make_float4(__int_as_float(i01), w01, __int_as_float(i11), w11);
            }
        }

        // prefetch next query's inputs
        if (i + 1 < CHUNK) {
            const int nq = bq + 1;
            myoff = g_off[(size_t)nq * 256 + h * 32 + lane];
            logit = (lane < 16) ? g_attn[(size_t)nq * 128 + h * 16 + lane] : -1e30f;
            myref = (lane < 8)  ? refp[(size_t)nq * 8 + lane] : 0.0f;
        }
        __syncwarp();

        float4 acc = make_float4(0.0f, 0.0f, 0.0f, 0.0f);
#pragma unroll
        for (int p = 0; p < 16; p++) {
            float2 pr = *(const float2*)&smp[h][p][2 * c];
            float w = pr.y;
            uint2 raw = __ldg((const uint2*)(vb + __float_as_int(pr.x)));
            float2 v01 = __half22float2(*(const __half2*)&raw.x);
            float2 v23 = __half22float2(*(const __half2*)&raw.y);
            acc.x = fmaf(w, v01.x, acc.x);
            acc.y = fmaf(w, v01.y, acc.y);
            acc.z = fmaf(w, v23.x, acc.z);
            acc.w = fmaf(w, v23.y, acc.w);
        }
#pragma unroll
        for (int o = 8; o <= 16; o <<= 1) {
            acc.x += __shfl_xor_sync(FULL, acc.x, o);
            acc.y += __shfl_xor_sync(FULL, acc.y, o);
            acc.z += __shfl_xor_sync(FULL, acc.z, o);
            acc.w += __shfl_xor_sync(FULL, acc.w, o);
        }

        if (lane < 8) {
            uint32_t h0,l0,h1,l1;
            split2(acc.x, acc.y, h0, l0);
            split2(acc.z, acc.w, h1, l1);
            size_t o8 = (size_t)bq * 256 + h * 32 + lane * 4;
            *(uint2*)&g_sh[o8] = make_uint2(h0, h1);
            *(uint2*)&g_sl[o8] = make_uint2(l0, l1);
        }
        __syncwarp();
    }
}

// ---------------------------------------------------------------------------
// kernel_launch
// Inputs: 0 query, 1 value, 2 reference_points, 3 spatial_shapes,
// 4 W_off, 5 b_off, 6 W_attn, 7 b_attn, 8 W_v, 9 b_v, 10 W_out, 11 b_out
// ---------------------------------------------------------------------------
extern "C" void kernel_launch(void* const* d_in, const int* in_sizes, int n_in,
                              void* d_out, int out_size) {
    const float* query = (const float*)d_in[0];
    const float* value = (const float*)d_in[1];
    const float* refp  = (const float*)d_in[2];
    const float* W_off = (const float*)d_in[4];
    const float* b_off = (const float*)d_in[5];
    const float* W_att = (const float*)d_in[6];
    const float* b_att = (const float*)d_in[7];
    const float* W_v   = (const float*)d_in[8];
    const float* b_v   = (const float*)d_in[9];
    const float* W_out = (const float*)d_in[10];
    const float* b_out = (const float*)d_in[11];
    float* out = (float*)d_out;

    cudaFuncSetAttribute(gemm_val, cudaFuncAttributeMaxDynamicSharedMemorySize, DSMEM_BYTES);
    cudaFuncSetAttribute(gemm_qoa, cudaFuncAttributeMaxDynamicSharedMemorySize, DSMEM_BYTES);
    cudaFuncSetAttribute(gemm_out, cudaFuncAttributeMaxDynamicSharedMemorySize, DSMEM_BYTES);

    dim3 blk(256);

    convert_acts<<<2 * (ACT_WORDS / 256), blk>>>(query, value);
    convert_wts<<<448, blk>>>(W_v, W_off, W_att, W_out);

    gemm_val<<<dim3(MROWS / 128, 2), blk, DSMEM_BYTES>>>(b_v);
    gemm_qoa<<<dim3(MROWS / 128, 3), blk, DSMEM_BYTES>>>(b_off, b_att);
    sampler<<<MROWS / CHUNK, blk>>>(refp);
    gemm_out<<<dim3(MROWS / 128, 2), blk, DSMEM_BYTES>>>(b_out, out);
}

// round 12
// speedup vs baseline: 1.4388x; 1.0537x over previous
#include <cuda_runtime.h>
#include <cuda_bf16.h>
#include <cuda_fp16.h>
#include <math.h>
#include <stdint.h>

// Problem constants (fixed by the reference)
#define BS 2
#define NQ 21760
#define NV 21760
#define MROWS (BS * NQ)   // 43520
#define CHUNK 16          // consecutive queries per sampler block

__device__ __constant__ int LVL_W[4] = {128, 64, 32, 16};
__device__ __constant__ int LVL_S[4] = {0, 16384, 20480, 21504};

// ---------------- scratch (allocation-free rule: __device__ globals) --------
__device__ __align__(16) __half g_val [MROWS * 256];   // value @ W_v + b_v (fp16)
__device__ float g_off [MROWS * 256];
__device__ float g_attn[MROWS * 128];

// tf32-rounded fp32 operands (bits in uint32)
__device__ __align__(16) uint32_t g_q   [MROWS * 256];   // rounded query
__device__ __align__(16) uint32_t g_vv  [MROWS * 256];   // rounded value
__device__ __align__(16) uint32_t g_samp[MROWS * 256];   // rounded sampler output
__device__ __align__(16) uint32_t gWv[256 * 256];
__device__ __align__(16) uint32_t gWo[256 * 256];
__device__ __align__(16) uint32_t gWa[256 * 128];
__device__ __align__(16) uint32_t gWu[256 * 256];

// ---------------------------------------------------------------------------
__device__ __forceinline__ uint32_t tf32r(float f) {
    uint32_t r;
    asm("cvt.rna.tf32.f32 %0, %1;" : "=r"(r) : "f"(f));
    return r;
}

__device__ __forceinline__ void mma_tf32(float *d, const uint32_t *a, const uint32_t *b) {
    asm volatile(
        "mma.sync.aligned.m16n8k8.row.col.f32.tf32.tf32.f32 "
        "{%0,%1,%2,%3}, {%4,%5,%6,%7}, {%8,%9}, {%0,%1,%2,%3};\n"
        : "+f"(d[0]), "+f"(d[1]), "+f"(d[2]), "+f"(d[3])
        : "r"(a[0]), "r"(a[1]), "r"(a[2]), "r"(a[3]), "r"(b[0]), "r"(b[1]));
}

__device__ __forceinline__ void cp16(uint32_t dst, const void* src) {
    asm volatile("cp.async.cg.shared.global [%0], [%1], 16;\n" :: "r"(dst), "l"(src));
}
__device__ __forceinline__ void cp_commit() { asm volatile("cp.async.commit_group;\n"); }
__device__ __forceinline__ void cp_wait1() { asm volatile("cp.async.wait_group 1;\n"); }
__device__ __forceinline__ void cp_wait0() { asm volatile("cp.async.wait_group 0;\n"); }

// ---------------------------------------------------------------------------
// Conversion kernels: element-wise tf32 rounding
// ---------------------------------------------------------------------------
#define ACT_WORDS (MROWS * 256 / 8)   // 8 floats per thread

__global__ __launch_bounds__(256)
void convert_acts(const float* __restrict__ query, const float* __restrict__ value) {
    int idx = blockIdx.x * 256 + threadIdx.x;
    const float* src; uint32_t* dst;
    if (idx < ACT_WORDS) { src = query; dst = g_q; }
    else { idx -= ACT_WORDS; src = value; dst = g_vv; }
    float4 f0 = *(const float4*)&src[idx * 8];
    float4 f1 = *(const float4*)&src[idx * 8 + 4];
    *(uint4*)&dst[idx * 8] =
        make_uint4(tf32r(f0.x), tf32r(f0.y), tf32r(f0.z), tf32r(f0.w));
    *(uint4*)&dst[idx * 8 + 4] =
        make_uint4(tf32r(f1.x), tf32r(f1.y), tf32r(f1.z), tf32r(f1.w));
}

// total weight floats: 65536 + 65536 + 32768 + 65536 = 229376 = 57344 float4
__global__ __launch_bounds__(256)
void convert_wts(const float* __restrict__ Wv, const float* __restrict__ Wo,
                 const float* __restrict__ Wa, const float* __restrict__ Wu) {
    int idx4 = blockIdx.x * 256 + threadIdx.x;
    const float* W; uint32_t* D;
    if (idx4 < 16384)      { W = Wv; D = gWv; }
    else if (idx4 < 32768) { idx4 -= 16384; W = Wo; D = gWo; }
    else if (idx4 < 40960) { idx4 -= 32768; W = Wa; D = gWa; }
    else                   { idx4 -= 40960; W = Wu; D = gWu; }
    float4 f = *(const float4*)&W[idx4 * 4];
    *(uint4*)&D[idx4 * 4] = make_uint4(tf32r(f.x), tf32r(f.y), tf32r(f.z), tf32r(f.w));
}

// ---------------------------------------------------------------------------
// tf32 GEMM: C[M,N] = A @ B + bias, single pass.
// Tile 128x128, BK=16 (2 x k8 MMA steps), 256 thr, warp tile 64x32.
// 3-stage cp.async pipeline, scalar LDS for A (stride 20 words, conflict-free)
// and B (stride 136 words, conflict-free). 32 MMA / iter / warp.
// ---------------------------------------------------------------------------
// dynamic smem: A: 3 bufs x 10240 (128 rows x 80B) @ 0
//               B: 3 bufs x 8704  (16 rows x 544B) @ 30720
#define A_BUF_B 10240
#define B_BUF_B 8704
#define OFF_B 30720
#define DSMEM_BYTES (30720 + 3 * 8704)   // 56832

template <bool HALF_OUT>
__device__ __forceinline__ void gemm_body(
    const uint32_t* __restrict__ Ag, const uint32_t* __restrict__ Bg,
    const float* __restrict__ bias, void* __restrict__ Cp,
    int N, int bm, int bn)
{
    extern __shared__ __align__(128) char dsm[];
    const uint32_t sbase = (uint32_t)__cvta_generic_to_shared(dsm);

    const int tid  = threadIdx.x;
    const int lane = tid & 31;
    const int warp = tid >> 5;
    const int g = lane >> 2;
    const int t = lane & 3;
    const int warp_m = (warp >> 2) * 64;
    const int warp_n = (warp & 3) * 32;

    // cp.async staging mapping
    const int ar  = tid >> 1;            // A row 0..127
    const int asi = (tid & 1) * 2;       // A 16B-seg 0 or 2 (of 4)
    const int br  = tid >> 4;            // B row 0..15
    const int bsi = (tid & 15) * 2;      // B 16B-seg 0..30 (of 32)

    const uint32_t aDst = ar * 80 + asi * 16;
    const uint32_t bDst = OFF_B + br * 544 + bsi * 16;
    const uint32_t* aSrc = Ag + (size_t)(bm + ar) * 256 + asi * 4;
    const uint32_t* bSrc = Bg + (size_t)br * N + bn + bsi * 4;

    float acc[4][4][4];
#pragma unroll
    for (int i = 0; i < 4; i++)
#pragma unroll
        for (int j = 0; j < 4; j++)
#pragma unroll
            for (int r = 0; r < 4; r++) acc[i][j][r] = 0.0f;

    auto load_chunk = [&](int stage, int buf) {
        cp16(sbase + buf * A_BUF_B + aDst, aSrc + stage * 16);
        cp16(sbase + buf * A_BUF_B + aDst + 16, aSrc + stage * 16 + 4);
        cp16(sbase + buf * B_BUF_B + bDst, bSrc + (size_t)stage * 16 * N);
        cp16(sbase + buf * B_BUF_B + bDst + 16, bSrc + (size_t)stage * 16 * N + 4);
        cp_commit();
    };

    load_chunk(0, 0);
    load_chunk(1, 1);

#pragma unroll
    for (int it = 0; it < 16; it++) {
        const int buf = it % 3;
        if (it < 15) cp_wait1(); else cp_wait0();
        __syncthreads();
        if (it < 14) load_chunk(it + 2, (it + 2) % 3);

        const uint32_t* Aw = (const uint32_t*)(dsm + buf * A_BUF_B);
        const uint32_t* Bw = (const uint32_t*)(dsm + OFF_B + buf * B_BUF_B);

#pragma unroll
        for (int s = 0; s < 2; s++) {
            uint32_t bf[4][2];
#pragma unroll
            for (int nt = 0; nt < 4; nt++) {
                int cb = warp_n + nt * 8 + g;
                bf[nt][0] = Bw[(8 * s + t) * 136 + cb];
                bf[nt][1] = Bw[(8 * s + t + 4) * 136 + cb];
            }
#pragma unroll
            for (int mt = 0; mt < 4; mt++) {
                uint32_t af[4];
                int rb = (warp_m + mt * 16 + g) * 20 + 8 * s + t;
                af[0] = Aw[rb];
                af[1] = Aw[rb + 160];
                af[2] = Aw[rb + 4];
                af[3] = Aw[rb + 164];
#pragma unroll
                for (int nt = 0; nt < 4; nt++) mma_tf32(acc[mt][nt], af, bf[nt]);
            }
        }
    }

    // epilogue
#pragma unroll
    for (int mt = 0; mt < 4; mt++) {
        int row0 = bm + warp_m + mt * 16 + g;
#pragma unroll
        for (int nt = 0; nt < 4; nt++) {
            int col = bn + warp_n + nt * 8 + 2 * t;
            float2 bv = *(const float2*)&bias[col];
            float vx0 = acc[mt][nt][0] + bv.x, vy0 = acc[mt][nt][1] + bv.y;
            float vx1 = acc[mt][nt][2] + bv.x, vy1 = acc[mt][nt][3] + bv.y;
            if (HALF_OUT) {
                __half* C = (__half*)Cp;
                *(__half2*)&C[(size_t)row0 * N + col] = __floats2half2_rn(vx0, vy0);
                *(__half2*)&C[(size_t)(row0 + 8) * N + col] = __floats2half2_rn(vx1, vy1);
            } else {
                float* C = (float*)Cp;
                *(float2*)&C[(size_t)row0 * N + col] = make_float2(vx0, vy0);
                *(float2*)&C[(size_t)(row0 + 8) * N + col] = make_float2(vx1, vy1);
            }
        }
    }
}

__global__ __launch_bounds__(256, 2)
void gemm_val(const float* __restrict__ bias) {
    gemm_body<true>(g_vv, gWv, bias, g_val, 256, blockIdx.x * 128, blockIdx.y * 128);
}

__global__ __launch_bounds__(256, 2)
void gemm_qoa(const float* __restrict__ b_off, const float* __restrict__ b_att) {
    if (blockIdx.y < 2)
        gemm_body<false>(g_q, gWo, b_off, g_off, 256, blockIdx.x * 128, blockIdx.y * 128);
    else
        gemm_body<false>(g_q, gWa, b_att, g_attn, 128, blockIdx.x * 128, 0);
}

__global__ __launch_bounds__(256, 2)
void gemm_out(const float* __restrict__ bias, float* __restrict__ out) {
    gemm_body<false>(g_samp, gWu, bias, out, 256, blockIdx.x * 128, blockIdx.y * 128);
}

// ---------------------------------------------------------------------------
// Deformable sampler: block = 8 warps = 8 heads, CHUNK consecutive queries.
// fp16 value gathers; outputs tf32-rounded fp32 g_samp (plain layout).
// ---------------------------------------------------------------------------
__global__ __launch_bounds__(256)
void sampler(const float* __restrict__ refp) {
    __shared__ __align__(16) float smp[8][16][8];
    const unsigned FULL = 0xffffffffu;
    const int h    = threadIdx.x >> 5;
    const int lane = threadIdx.x & 31;
    const int base = blockIdx.x * CHUNK;
    const int b    = (base >= NQ) ? 1 : 0;

    const int c = lane >> 3;
    const int u = lane & 7;
    const char* vb = (const char*)(g_val + (size_t)b * (NV * 256) + h * 32) + u * 8;

    float myoff = g_off[(size_t)base * 256 + h * 32 + lane];
    float logit = (lane < 16) ? g_attn[(size_t)base * 128 + h * 16 + lane] : -1e30f;
    float myref = (lane < 8)  ? refp[(size_t)base * 8 + lane] : 0.0f;

    for (int i = 0; i < CHUNK; i++) {
        const int bq = base + i;

        float m = logit;
#pragma unroll
        for (int o = 8; o > 0; o >>= 1) m = fmaxf(m, __shfl_xor_sync(FULL, m, o));
        float e = (lane < 16) ? __expf(logit - m) : 0.0f;
        float s = e;
#pragma unroll
        for (int o = 8; o > 0; o >>= 1) s += __shfl_xor_sync(FULL, s, o);
        float aw = e / s;

        {
            int p = lane & 15;
            int l = p >> 2;
            float ox = __shfl_sync(FULL, myoff, 2 * p);
            float oy = __shfl_sync(FULL, myoff, 2 * p + 1);
            float rx = __shfl_sync(FULL, myref, 2 * l);
            float ry = __shfl_sync(FULL, myref, 2 * l + 1);

            const int Wl = LVL_W[l];
            const int st = LVL_S[l];
            float x = rx * (float)Wl + ox - 0.5f;
            float y = ry * (float)Wl + oy - 0.5f;
            float xf = floorf(x), yf = floorf(y);
            int x0 = (int)xf, y0 = (int)yf;
            float fx = x - xf, fy = y - yf;

            float w00 = (1.0f - fx) * (1.0f - fy) * aw;
            float w10 = fx * (1.0f - fy) * aw;
            float w01 = (1.0f - fx) * fy * aw;
            float w11 = fx * fy * aw;

            bool vx0 = (x0 >= 0) && (x0 < Wl);
            bool vx1 = (x0 + 1 >= 0) && (x0 + 1 < Wl);
            bool vy0 = (y0 >= 0) && (y0 < Wl);
            bool vy1 = (y0 + 1 >= 0) && (y0 + 1 < Wl);
            w00 = (vx0 && vy0) ? w00 : 0.0f;
            w10 = (vx1 && vy0) ? w10 : 0.0f;
            w01 = (vx0 && vy1) ? w01 : 0.0f;
            w11 = (vx1 && vy1) ? w11 : 0.0f;

            int xc0 = min(max(x0, 0), Wl - 1);
            int xc1 = min(max(x0 + 1, 0), Wl - 1);
            int yc0 = min(max(y0, 0), Wl - 1);
            int yc1 = min(max(y0 + 1, 0), Wl - 1);

            // byte offsets: element idx * 256 halves * 2B = << 9
            int i00 = (st + yc0 * Wl + xc0) << 9;
            int i10 = (st + yc0 * Wl + xc1) << 9;
            int i01 = (st + yc1 * Wl + xc0) << 9;
            int i11 = (st + yc1 * Wl + xc1) << 9;

            if (lane < 16) {
                *(float4*)&smp[h][p][0] =
                    make_float4(__int_as_float(i00), w00, __int_as_float(i10), w10);
                *(float4*)&smp[h][p][4] =
                    make_float4(__int_as_float(i01), w01, __int_as_float(i11), w11);
            }
        }

        if (i + 1 < CHUNK) {
            const int nq = bq + 1;
            myoff = g_off[(size_t)nq * 256 + h * 32 + lane];
            logit = (lane < 16) ? g_attn[(size_t)nq * 128 + h * 16 + lane] : -1e30f;
            myref = (lane < 8)  ? refp[(size_t)nq * 8 + lane] : 0.0f;
        }
        __syncwarp();

        float4 acc = make_float4(0.0f, 0.0f, 0.0f, 0.0f);
#pragma unroll
        for (int p = 0; p < 16; p++) {
            float2 pr = *(const float2*)&smp[h][p][2 * c];
            float w = pr.y;
            uint2 raw = __ldg((const uint2*)(vb + __float_as_int(pr.x)));
            float2 v01 = __half22float2(*(const __half2*)&raw.x);
            float2 v23 = __half22float2(*(const __half2*)&raw.y);
            acc.x = fmaf(w, v01.x, acc.x);
            acc.y = fmaf(w, v01.y, acc.y);
            acc.z = fmaf(w, v23.x, acc.z);
            acc.w = fmaf(w, v23.y, acc.w);
        }
#pragma unroll
        for (int o = 8; o <= 16; o <<= 1) {
            acc.x += __shfl_xor_sync(FULL, acc.x, o);
            acc.y += __shfl_xor_sync(FULL, acc.y, o);
            acc.z += __shfl_xor_sync(FULL, acc.z, o);
            acc.w += __shfl_xor_sync(FULL, acc.w, o);
        }

        if (lane < 8) {
            *(uint4*)&g_samp[(size_t)bq * 256 + h * 32 + lane * 4] =
                make_uint4(tf32r(acc.x), tf32r(acc.y), tf32r(acc.z), tf32r(acc.w));
        }
        __syncwarp();
    }
}

// ---------------------------------------------------------------------------
// kernel_launch
// Inputs: 0 query, 1 value, 2 reference_points, 3 spatial_shapes,
// 4 W_off, 5 b_off, 6 W_attn, 7 b_attn, 8 W_v, 9 b_v, 10 W_out, 11 b_out
// ---------------------------------------------------------------------------
extern "C" void kernel_launch(void* const* d_in, const int* in_sizes, int n_in,
                              void* d_out, int out_size) {
    const float* query = (const float*)d_in[0];
    const float* value = (const float*)d_in[1];
    const float* refp  = (const float*)d_in[2];
    const float* W_off = (const float*)d_in[4];
    const float* b_off = (const float*)d_in[5];
    const float* W_att = (const float*)d_in[6];
    const float* b_att = (const float*)d_in[7];
    const float* W_v   = (const float*)d_in[8];
    const float* b_v   = (const float*)d_in[9];
    const float* W_out = (const float*)d_in[10];
    const float* b_out = (const float*)d_in[11];
    float* out = (float*)d_out;

    cudaFuncSetAttribute(gemm_val, cudaFuncAttributeMaxDynamicSharedMemorySize, DSMEM_BYTES);
    cudaFuncSetAttribute(gemm_qoa, cudaFuncAttributeMaxDynamicSharedMemorySize, DSMEM_BYTES);
    cudaFuncSetAttribute(gemm_out, cudaFuncAttributeMaxDynamicSharedMemorySize, DSMEM_BYTES);

    dim3 blk(256);

    convert_acts<<<2 * (ACT_WORDS / 256), blk>>>(query, value);
    convert_wts<<<224, blk>>>(W_v, W_off, W_att, W_out);

    gemm_val<<<dim3(MROWS / 128, 2), blk, DSMEM_BYTES>>>(b_v);
    gemm_qoa<<<dim3(MROWS / 128, 3), blk, DSMEM_BYTES>>>(b_off, b_att);
    sampler<<<MROWS / CHUNK, blk>>>(refp);
    gemm_out<<<dim3(MROWS / 128, 2), blk, DSMEM_BYTES>>>(b_out, out);
}

// round 14
// speedup vs baseline: 1.5816x; 1.0992x over previous
#include <cuda_runtime.h>
#include <cuda_bf16.h>
#include <cuda_fp16.h>
#include <math.h>
#include <stdint.h>

// Problem constants (fixed by the reference)
#define BS 2
#define NQ 21760
#define NV 21760
#define MROWS (BS * NQ)   // 43520
#define CHUNK 16          // consecutive queries per sampler block

__device__ __constant__ int LVL_W[4] = {128, 64, 32, 16};
__device__ __constant__ int LVL_S[4] = {0, 16384, 20480, 21504};

// ---------------- scratch (allocation-free rule: __device__ globals) --------
__device__ __align__(16) __half g_val [MROWS * 256];   // value @ W_v + b_v (fp16)
__device__ float g_off [MROWS * 256];
__device__ float g_attn[MROWS * 128];

// tf32-rounded fp32 operands (bits in uint32)
__device__ __align__(16) uint32_t g_q   [MROWS * 256];
__device__ __align__(16) uint32_t g_vv  [MROWS * 256];
__device__ __align__(16) uint32_t g_samp[MROWS * 256];
__device__ __align__(16) uint32_t gWv[256 * 256];
__device__ __align__(16) uint32_t gWo[256 * 256];
__device__ __align__(16) uint32_t gWa[256 * 128];
__device__ __align__(16) uint32_t gWu[256 * 256];

// ---------------------------------------------------------------------------
__device__ __forceinline__ uint32_t tf32r(float f) {
    uint32_t r;
    asm("cvt.rna.tf32.f32 %0, %1;" : "=r"(r) : "f"(f));
    return r;
}

__device__ __forceinline__ void mma_tf32(float *d, const uint32_t *a, const uint32_t *b) {
    asm volatile(
        "mma.sync.aligned.m16n8k8.row.col.f32.tf32.tf32.f32 "
        "{%0,%1,%2,%3}, {%4,%5,%6,%7}, {%8,%9}, {%0,%1,%2,%3};\n"
        : "+f"(d[0]), "+f"(d[1]), "+f"(d[2]), "+f"(d[3])
        : "r"(a[0]), "r"(a[1]), "r"(a[2]), "r"(a[3]), "r"(b[0]), "r"(b[1]));
}

__device__ __forceinline__ void cp16(uint32_t dst, const void* src) {
    asm volatile("cp.async.cg.shared.global [%0], [%1], 16;\n" :: "r"(dst), "l"(src));
}
__device__ __forceinline__ void cp_commit() { asm volatile("cp.async.commit_group;\n"); }
__device__ __forceinline__ void cp_wait1() { asm volatile("cp.async.wait_group 1;\n"); }
__device__ __forceinline__ void cp_wait0() { asm volatile("cp.async.wait_group 0;\n"); }

// ---------------------------------------------------------------------------
// Conversion kernels: element-wise tf32 rounding
// ---------------------------------------------------------------------------
#define ACT_WORDS (MROWS * 256 / 8)   // 8 floats per thread

__global__ __launch_bounds__(256)
void convert_acts(const float* __restrict__ query, const float* __restrict__ value) {
    int idx = blockIdx.x * 256 + threadIdx.x;
    const float* src; uint32_t* dst;
    if (idx < ACT_WORDS) { src = query; dst = g_q; }
    else { idx -= ACT_WORDS; src = value; dst = g_vv; }
    float4 f0 = *(const float4*)&src[idx * 8];
    float4 f1 = *(const float4*)&src[idx * 8 + 4];
    *(uint4*)&dst[idx * 8] =
        make_uint4(tf32r(f0.x), tf32r(f0.y), tf32r(f0.z), tf32r(f0.w));
    *(uint4*)&dst[idx * 8 + 4] =
        make_uint4(tf32r(f1.x), tf32r(f1.y), tf32r(f1.z), tf32r(f1.w));
}

__global__ __launch_bounds__(256)
void convert_wts(const float* __restrict__ Wv, const float* __restrict__ Wo,
                 const float* __restrict__ Wa, const float* __restrict__ Wu) {
    int idx4 = blockIdx.x * 256 + threadIdx.x;
    const float* W; uint32_t* D;
    if (idx4 < 16384)      { W = Wv; D = gWv; }
    else if (idx4 < 32768) { idx4 -= 16384; W = Wo; D = gWo; }
    else if (idx4 < 40960) { idx4 -= 32768; W = Wa; D = gWa; }
    else                   { idx4 -= 40960; W = Wu; D = gWu; }
    float4 f = *(const float4*)&W[idx4 * 4];
    *(uint4*)&D[idx4 * 4] = make_uint4(tf32r(f.x), tf32r(f.y), tf32r(f.z), tf32r(f.w));
}

// ---------------------------------------------------------------------------
// tf32 GEMM: C[M,N] = A @ B + bias, single pass.
// Tile 128x128, BK=16 (2 x k8 MMA steps), 256 thr, warp tile 64x32.
// 3-stage cp.async pipeline, scalar LDS for A/B (conflict-free padded).
// ---------------------------------------------------------------------------
#define A_BUF_B 10240
#define B_BUF_B 8704
#define OFF_B 30720
#define DSMEM_BYTES (30720 + 3 * 8704)   // 56832

template <bool HALF_OUT>
__device__ __forceinline__ void gemm_body(
    const uint32_t* __restrict__ Ag, const uint32_t* __restrict__ Bg,
    const float* __restrict__ bias, void* __restrict__ Cp,
    int N, int bm, int bn)
{
    extern __shared__ __align__(128) char dsm[];
    const uint32_t sbase = (uint32_t)__cvta_generic_to_shared(dsm);

    const int tid  = threadIdx.x;
    const int lane = tid & 31;
    const int warp = tid >> 5;
    const int g = lane >> 2;
    const int t = lane & 3;
    const int warp_m = (warp >> 2) * 64;
    const int warp_n = (warp & 3) * 32;

    const int ar  = tid >> 1;
    const int asi = (tid & 1) * 2;
    const int br  = tid >> 4;
    const int bsi = (tid & 15) * 2;

    const uint32_t aDst = ar * 80 + asi * 16;
    const uint32_t bDst = OFF_B + br * 544 + bsi * 16;
    const uint32_t* aSrc = Ag + (size_t)(bm + ar) * 256 + asi * 4;
    const uint32_t* bSrc = Bg + (size_t)br * N + bn + bsi * 4;

    float acc[4][4][4];
#pragma unroll
    for (int i = 0; i < 4; i++)
#pragma unroll
        for (int j = 0; j < 4; j++)
#pragma unroll
            for (int r = 0; r < 4; r++) acc[i][j][r] = 0.0f;

    auto load_chunk = [&](int stage, int buf) {
        cp16(sbase + buf * A_BUF_B + aDst, aSrc + stage * 16);
        cp16(sbase + buf * A_BUF_B + aDst + 16, aSrc + stage * 16 + 4);
        cp16(sbase + buf * B_BUF_B + bDst, bSrc + (size_t)stage * 16 * N);
        cp16(sbase + buf * B_BUF_B + bDst + 16, bSrc + (size_t)stage * 16 * N + 4);
        cp_commit();
    };

    load_chunk(0, 0);
    load_chunk(1, 1);

#pragma unroll
    for (int it = 0; it < 16; it++) {
        const int buf = it % 3;
        if (it < 15) cp_wait1(); else cp_wait0();
        __syncthreads();
        if (it < 14) load_chunk(it + 2, (it + 2) % 3);

        const uint32_t* Aw = (const uint32_t*)(dsm + buf * A_BUF_B);
        const uint32_t* Bw = (const uint32_t*)(dsm + OFF_B + buf * B_BUF_B);

#pragma unroll
        for (int s = 0; s < 2; s++) {
            uint32_t bf[4][2];
#pragma unroll
            for (int nt = 0; nt < 4; nt++) {
                int cb = warp_n + nt * 8 + g;
                bf[nt][0] = Bw[(8 * s + t) * 136 + cb];
                bf[nt][1] = Bw[(8 * s + t + 4) * 136 + cb];
            }
#pragma unroll
            for (int mt = 0; mt < 4; mt++) {
                uint32_t af[4];
                int rb = (warp_m + mt * 16 + g) * 20 + 8 * s + t;
                af[0] = Aw[rb];
                af[1] = Aw[rb + 160];
                af[2] = Aw[rb + 4];
                af[3] = Aw[rb + 164];
#pragma unroll
                for (int nt = 0; nt < 4; nt++) mma_tf32(acc[mt][nt], af, bf[nt]);
            }
        }
    }

    // epilogue
#pragma unroll
    for (int mt = 0; mt < 4; mt++) {
        int row0 = bm + warp_m + mt * 16 + g;
#pragma unroll
        for (int nt = 0; nt < 4; nt++) {
            int col = bn + warp_n + nt * 8 + 2 * t;
            float2 bv = *(const float2*)&bias[col];
            float vx0 = acc[mt][nt][0] + bv.x, vy0 = acc[mt][nt][1] + bv.y;
            float vx1 = acc[mt][nt][2] + bv.x, vy1 = acc[mt][nt][3] + bv.y;
            if (HALF_OUT) {
                __half* C = (__half*)Cp;
                *(__half2*)&C[(size_t)row0 * N + col] = __floats2half2_rn(vx0, vy0);
                *(__half2*)&C[(size_t)(row0 + 8) * N + col] = __floats2half2_rn(vx1, vy1);
            } else {
                float* C = (float*)Cp;
                *(float2*)&C[(size_t)row0 * N + col] = make_float2(vx0, vy0);
                *(float2*)&C[(size_t)(row0 + 8) * N + col] = make_float2(vx1, vy1);
            }
        }
    }
}

// merged: y=0,1 -> val (N=256); y=2,3 -> off (N=256); y=4 -> attn (N=128)
__global__ __launch_bounds__(256, 2)
void gemm_vqa(const float* __restrict__ b_v, const float* __restrict__ b_off,
              const float* __restrict__ b_att) {
    int bm = blockIdx.x * 128;
    int y = blockIdx.y;
    if (y < 2)
        gemm_body<true>(g_vv, gWv, b_v, g_val, 256, bm, y * 128);
    else if (y < 4)
        gemm_body<false>(g_q, gWo, b_off, g_off, 256, bm, (y - 2) * 128);
    else
        gemm_body<false>(g_q, gWa, b_att, g_attn, 128, bm, 0);
}

__global__ __launch_bounds__(256, 2)
void gemm_out(const float* __restrict__ bias, float* __restrict__ out) {
    gemm_body<false>(g_samp, gWu, bias, out, 256, blockIdx.x * 128, blockIdx.y * 128);
}

// ---------------------------------------------------------------------------
// Deformable sampler v4: block = 8 warps = 8 heads, CHUNK consecutive queries,
// processed in PAIRS. Lanes 0..15 = query i's 16 points, lanes 16..31 =
// query i+1's. One softmax serves both (xor widths <=8 stay in each half).
// Offsets/refs loaded directly per lane (no register staging / shfl).
// ---------------------------------------------------------------------------
__global__ __launch_bounds__(256)
void sampler(const float* __restrict__ refp) {
    __shared__ __align__(16) float smp[8][32][8];
    const unsigned FULL = 0xffffffffu;
    const int h    = threadIdx.x >> 5;
    const int lane = threadIdx.x & 31;
    const int base = blockIdx.x * CHUNK;
    const int b    = (base >= NQ) ? 1 : 0;

    const int c = lane >> 3;
    const int u = lane & 7;
    const char* vb = (const char*)(g_val + (size_t)b * (NV * 256) + h * 32) + u * 8;

    const int qi = lane >> 4;     // which query of the pair this lane serves
    const int p  = lane & 15;     // point id
    const int l  = p >> 2;        // level
    const int Wl = LVL_W[l];
    const int st = LVL_S[l];

    for (int i = 0; i < CHUNK; i += 2) {
        const int bq  = base + i;
        const int bq2 = bq + qi;

        // paired softmax: all 32 lanes hold real logits
        float logit = g_attn[(size_t)bq2 * 128 + h * 16 + p];
        float m = logit;
#pragma unroll
        for (int o = 8; o > 0; o >>= 1) m = fmaxf(m, __shfl_xor_sync(FULL, m, o));
        float e = __expf(logit - m);
        float s = e;
#pragma unroll
        for (int o = 8; o > 0; o >>= 1) s += __shfl_xor_sync(FULL, s, o);
        float aw = e / s;

        // per-point precompute: direct loads, all 32 lanes
        {
            float2 offv = *(const float2*)&g_off[(size_t)bq2 * 256 + h * 32 + 2 * p];
            float2 refv = *(const float2*)&refp[(size_t)bq2 * 8 + 2 * l];

            float x = refv.x * (float)Wl + offv.x - 0.5f;
            float y = refv.y * (float)Wl + offv.y - 0.5f;
            float xf = floorf(x), yf = floorf(y);
            int x0 = (int)xf, y0 = (int)yf;
            float fx = x - xf, fy = y - yf;

            float w00 = (1.0f - fx) * (1.0f - fy) * aw;
            float w10 = fx * (1.0f - fy) * aw;
            float w01 = (1.0f - fx) * fy * aw;
            float w11 = fx * fy * aw;

            bool vx0 = (x0 >= 0) && (x0 < Wl);
            bool vx1 = (x0 + 1 >= 0) && (x0 + 1 < Wl);
            bool vy0 = (y0 >= 0) && (y0 < Wl);
            bool vy1 = (y0 + 1 >= 0) && (y0 + 1 < Wl);
            w00 = (vx0 && vy0) ? w00 : 0.0f;
            w10 = (vx1 && vy0) ? w10 : 0.0f;
            w01 = (vx0 && vy1) ? w01 : 0.0f;
            w11 = (vx1 && vy1) ? w11 : 0.0f;

            int xc0 = min(max(x0, 0), Wl - 1);
            int xc1 = min(max(x0 + 1, 0), Wl - 1);
            int yc0 = min(max(y0, 0), Wl - 1);
            int yc1 = min(max(y0 + 1, 0), Wl - 1);

            // byte offsets: element idx * 256 halves * 2B = << 9
            int i00 = (st + yc0 * Wl + xc0) << 9;
            int i10 = (st + yc0 * Wl + xc1) << 9;
            int i01 = (st + yc1 * Wl + xc0) << 9;
            int i11 = (st + yc1 * Wl + xc1) << 9;

            *(float4*)&smp[h][lane][0] =
                make_float4(__int_as_float(i00), w00, __int_as_float(i10), w10);
            *(float4*)&smp[h][lane][4] =
                make_float4(__int_as_float(i01), w01, __int_as_float(i11), w11);
        }
        __syncwarp();

        // gather both queries of the pair
#pragma unroll
        for (int qq = 0; qq < 2; qq++) {
            float4 acc = make_float4(0.0f, 0.0f, 0.0f, 0.0f);
#pragma unroll
            for (int pp = 0; pp < 16; pp++) {
                float2 pr = *(const float2*)&smp[h][qq * 16 + pp][2 * c];
                float w = pr.y;
                uint2 raw = __ldg((const uint2*)(vb + __float_as_int(pr.x)));
                float2 v01 = __half22float2(*(const __half2*)&raw.x);
                float2 v23 = __half22float2(*(const __half2*)&raw.y);
                acc.x = fmaf(w, v01.x, acc.x);
                acc.y = fmaf(w, v01.y, acc.y);
                acc.z = fmaf(w, v23.x, acc.z);
                acc.w = fmaf(w, v23.y, acc.w);
            }
#pragma unroll
            for (int o = 8; o <= 16; o <<= 1) {
                acc.x += __shfl_xor_sync(FULL, acc.x, o);
                acc.y += __shfl_xor_sync(FULL, acc.y, o);
                acc.z += __shfl_xor_sync(FULL, acc.z, o);
                acc.w += __shfl_xor_sync(FULL, acc.w, o);
            }
            if (lane < 8) {
                *(uint4*)&g_samp[(size_t)(bq + qq) * 256 + h * 32 + lane * 4] =
                    make_uint4(tf32r(acc.x), tf32r(acc.y), tf32r(acc.z), tf32r(acc.w));
            }
        }
        __syncwarp();   // guard smp reuse across pair iterations
    }
}

// ---------------------------------------------------------------------------
// kernel_launch
// Inputs: 0 query, 1 value, 2 reference_points, 3 spatial_shapes,
// 4 W_off, 5 b_off, 6 W_attn, 7 b_attn, 8 W_v, 9 b_v, 10 W_out, 11 b_out
// ---------------------------------------------------------------------------
extern "C" void kernel_launch(void* const* d_in, const int* in_sizes, int n_in,
                              void* d_out, int out_size) {
    const float* query = (const float*)d_in[0];
    const float* value = (const float*)d_in[1];
    const float* refp  = (const float*)d_in[2];
    const float* W_off = (const float*)d_in[4];
    const float* b_off = (const float*)d_in[5];
    const float* W_att = (const float*)d_in[6];
    const float* b_att = (const float*)d_in[7];
    const float* W_v   = (const float*)d_in[8];
    const float* b_v   = (const float*)d_in[9];
    const float* W_out = (const float*)d_in[10];
    const float* b_out = (const float*)d_in[11];
    float* out = (float*)d_out;

    cudaFuncSetAttribute(gemm_vqa, cudaFuncAttributeMaxDynamicSharedMemorySize, DSMEM_BYTES);
    cudaFuncSetAttribute(gemm_out, cudaFuncAttributeMaxDynamicSharedMemorySize, DSMEM_BYTES);

    dim3 blk(256);

    convert_acts<<<2 * (ACT_WORDS / 256), blk>>>(query, value);
    convert_wts<<<224, blk>>>(W_v, W_off, W_att, W_out);

    gemm_vqa<<<dim3(MROWS / 128, 5), blk, DSMEM_BYTES>>>(b_v, b_off, b_att);
    sampler<<<MROWS / CHUNK, blk>>>(refp);
    gemm_out<<<dim3(MROWS / 128, 2), blk, DSMEM_BYTES>>>(b_out, out);
}

// round 15
// speedup vs baseline: 1.5865x; 1.0031x over previous
#include <cuda_runtime.h>
#include <cuda_bf16.h>
#include <cuda_fp16.h>
#include <math.h>
#include <stdint.h>

// Problem constants (fixed by the reference)
#define BS 2
#define NQ 21760
#define NV 21760
#define MROWS (BS * NQ)   // 43520
#define CHUNK 16          // consecutive queries per sampler block

__device__ __constant__ int LVL_W[4] = {128, 64, 32, 16};
__device__ __constant__ int LVL_S[4] = {0, 16384, 20480, 21504};

// ---------------- scratch (allocation-free rule: __device__ globals) --------
// g_val is HEAD-MAJOR: [b][h][pixel][32ch] fp16 (64B per pixel per head)
__device__ __align__(16) __half g_val [MROWS * 256];
__device__ float g_off [MROWS * 256];
__device__ float g_attn[MROWS * 128];

// tf32-rounded fp32 operands (bits in uint32)
__device__ __align__(16) uint32_t g_q   [MROWS * 256];
__device__ __align__(16) uint32_t g_vv  [MROWS * 256];
__device__ __align__(16) uint32_t g_samp[MROWS * 256];
__device__ __align__(16) uint32_t gWv[256 * 256];
__device__ __align__(16) uint32_t gWo[256 * 256];
__device__ __align__(16) uint32_t gWa[256 * 128];
__device__ __align__(16) uint32_t gWu[256 * 256];

// ---------------------------------------------------------------------------
__device__ __forceinline__ uint32_t tf32r(float f) {
    uint32_t r;
    asm("cvt.rna.tf32.f32 %0, %1;" : "=r"(r) : "f"(f));
    return r;
}

__device__ __forceinline__ void mma_tf32(float *d, const uint32_t *a, const uint32_t *b) {
    asm volatile(
        "mma.sync.aligned.m16n8k8.row.col.f32.tf32.tf32.f32 "
        "{%0,%1,%2,%3}, {%4,%5,%6,%7}, {%8,%9}, {%0,%1,%2,%3};\n"
        : "+f"(d[0]), "+f"(d[1]), "+f"(d[2]), "+f"(d[3])
        : "r"(a[0]), "r"(a[1]), "r"(a[2]), "r"(a[3]), "r"(b[0]), "r"(b[1]));
}

__device__ __forceinline__ void cp16(uint32_t dst, const void* src) {
    asm volatile("cp.async.cg.shared.global [%0], [%1], 16;\n" :: "r"(dst), "l"(src));
}
__device__ __forceinline__ void cp_commit() { asm volatile("cp.async.commit_group;\n"); }
__device__ __forceinline__ void cp_wait1() { asm volatile("cp.async.wait_group 1;\n"); }
__device__ __forceinline__ void cp_wait0() { asm volatile("cp.async.wait_group 0;\n"); }

// ---------------------------------------------------------------------------
// Conversion kernels: element-wise tf32 rounding
// ---------------------------------------------------------------------------
#define ACT_WORDS (MROWS * 256 / 8)   // 8 floats per thread

__global__ __launch_bounds__(256)
void convert_acts(const float* __restrict__ query, const float* __restrict__ value) {
    int idx = blockIdx.x * 256 + threadIdx.x;
    const float* src; uint32_t* dst;
    if (idx < ACT_WORDS) { src = query; dst = g_q; }
    else { idx -= ACT_WORDS; src = value; dst = g_vv; }
    float4 f0 = *(const float4*)&src[idx * 8];
    float4 f1 = *(const float4*)&src[idx * 8 + 4];
    *(uint4*)&dst[idx * 8] =
        make_uint4(tf32r(f0.x), tf32r(f0.y), tf32r(f0.z), tf32r(f0.w));
    *(uint4*)&dst[idx * 8 + 4] =
        make_uint4(tf32r(f1.x), tf32r(f1.y), tf32r(f1.z), tf32r(f1.w));
}

__global__ __launch_bounds__(256)
void convert_wts(const float* __restrict__ Wv, const float* __restrict__ Wo,
                 const float* __restrict__ Wa, const float* __restrict__ Wu) {
    int idx4 = blockIdx.x * 256 + threadIdx.x;
    const float* W; uint32_t* D;
    if (idx4 < 16384)      { W = Wv; D = gWv; }
    else if (idx4 < 32768) { idx4 -= 16384; W = Wo; D = gWo; }
    else if (idx4 < 40960) { idx4 -= 32768; W = Wa; D = gWa; }
    else                   { idx4 -= 40960; W = Wu; D = gWu; }
    float4 f = *(const float4*)&W[idx4 * 4];
    *(uint4*)&D[idx4 * 4] = make_uint4(tf32r(f.x), tf32r(f.y), tf32r(f.z), tf32r(f.w));
}

// ---------------------------------------------------------------------------
// tf32 GEMM: C[M,N] = A @ B + bias, single pass.
// Tile 128x128, BK=16 (2 x k8 MMA steps), 256 thr, warp tile 64x32.
// 3-stage cp.async pipeline, scalar LDS for A/B (conflict-free padded).
// HALF_OUT stores head-major fp16 into g_val.
// ---------------------------------------------------------------------------
#define A_BUF_B 10240
#define B_BUF_B 8704
#define OFF_B 30720
#define DSMEM_BYTES (30720 + 3 * 8704)   // 56832

template <bool HALF_OUT>
__device__ __forceinline__ void gemm_body(
    const uint32_t* __restrict__ Ag, const uint32_t* __restrict__ Bg,
    const float* __restrict__ bias, void* __restrict__ Cp,
    int N, int bm, int bn)
{
    extern __shared__ __align__(128) char dsm[];
    const uint32_t sbase = (uint32_t)__cvta_generic_to_shared(dsm);

    const int tid  = threadIdx.x;
    const int lane = tid & 31;
    const int warp = tid >> 5;
    const int g = lane >> 2;
    const int t = lane & 3;
    const int warp_m = (warp >> 2) * 64;
    const int warp_n = (warp & 3) * 32;

    const int ar  = tid >> 1;
    const int asi = (tid & 1) * 2;
    const int br  = tid >> 4;
    const int bsi = (tid & 15) * 2;

    const uint32_t aDst = ar * 80 + asi * 16;
    const uint32_t bDst = OFF_B + br * 544 + bsi * 16;
    const uint32_t* aSrc = Ag + (size_t)(bm + ar) * 256 + asi * 4;
    const uint32_t* bSrc = Bg + (size_t)br * N + bn + bsi * 4;

    float acc[4][4][4];
#pragma unroll
    for (int i = 0; i < 4; i++)
#pragma unroll
        for (int j = 0; j < 4; j++)
#pragma unroll
            for (int r = 0; r < 4; r++) acc[i][j][r] = 0.0f;

    auto load_chunk = [&](int stage, int buf) {
        cp16(sbase + buf * A_BUF_B + aDst, aSrc + stage * 16);
        cp16(sbase + buf * A_BUF_B + aDst + 16, aSrc + stage * 16 + 4);
        cp16(sbase + buf * B_BUF_B + bDst, bSrc + (size_t)stage * 16 * N);
        cp16(sbase + buf * B_BUF_B + bDst + 16, bSrc + (size_t)stage * 16 * N + 4);
        cp_commit();
    };

    load_chunk(0, 0);
    load_chunk(1, 1);

#pragma unroll
    for (int it = 0; it < 16; it++) {
        const int buf = it % 3;
        if (it < 15) cp_wait1(); else cp_wait0();
        __syncthreads();
        if (it < 14) load_chunk(it + 2, (it + 2) % 3);

        const uint32_t* Aw = (const uint32_t*)(dsm + buf * A_BUF_B);
        const uint32_t* Bw = (const uint32_t*)(dsm + OFF_B + buf * B_BUF_B);

#pragma unroll
        for (int s = 0; s < 2; s++) {
            uint32_t bf[4][2];
#pragma unroll
            for (int nt = 0; nt < 4; nt++) {
                int cb = warp_n + nt * 8 + g;
                bf[nt][0] = Bw[(8 * s + t) * 136 + cb];
                bf[nt][1] = Bw[(8 * s + t + 4) * 136 + cb];
            }
#pragma unroll
            for (int mt = 0; mt < 4; mt++) {
                uint32_t af[4];
                int rb = (warp_m + mt * 16 + g) * 20 + 8 * s + t;
                af[0] = Aw[rb];
                af[1] = Aw[rb + 160];
                af[2] = Aw[rb + 4];
                af[3] = Aw[rb + 164];
#pragma unroll
                for (int nt = 0; nt < 4; nt++) mma_tf32(acc[mt][nt], af, bf[nt]);
            }
        }
    }

    // epilogue
    const int bb = (bm >= NQ) ? 1 : 0;   // batch (blocks never straddle)
#pragma unroll
    for (int mt = 0; mt < 4; mt++) {
        int row0 = bm + warp_m + mt * 16 + g;
#pragma unroll
        for (int nt = 0; nt < 4; nt++) {
            int col = bn + warp_n + nt * 8 + 2 * t;
            float2 bv = *(const float2*)&bias[col];
            float vx0 = acc[mt][nt][0] + bv.x, vy0 = acc[mt][nt][1] + bv.y;
            float vx1 = acc[mt][nt][2] + bv.x, vy1 = acc[mt][nt][3] + bv.y;
            if (HALF_OUT) {
                // head-major scatter: [b][h][pix][32ch]
                __half* C = (__half*)Cp;
                int hh = col >> 5, ch = col & 31;
                int pix0 = row0 - bb * NQ;
                size_t base = ((size_t)(bb * 8 + hh) * NV);
                *(__half2*)&C[(base + pix0) * 32 + ch] = __floats2half2_rn(vx0, vy0);
                *(__half2*)&C[(base + pix0 + 8) * 32 + ch] = __floats2half2_rn(vx1, vy1);
            } else {
                float* C = (float*)Cp;
                *(float2*)&C[(size_t)row0 * N + col] = make_float2(vx0, vy0);
                *(float2*)&C[(size_t)(row0 + 8) * N + col] = make_float2(vx1, vy1);
            }
        }
    }
}

// merged: y=0,1 -> val (N=256); y=2,3 -> off (N=256); y=4 -> attn (N=128)
__global__ __launch_bounds__(256, 2)
void gemm_vqa(const float* __restrict__ b_v, const float* __restrict__ b_off,
              const float* __restrict__ b_att) {
    int bm = blockIdx.x * 128;
    int y = blockIdx.y;
    if (y < 2)
        gemm_body<true>(g_vv, gWv, b_v, g_val, 256, bm, y * 128);
    else if (y < 4)
        gemm_body<false>(g_q, gWo, b_off, g_off, 256, bm, (y - 2) * 128);
    else
        gemm_body<false>(g_q, gWa, b_att, g_attn, 128, bm, 0);
}

__global__ __launch_bounds__(256, 2)
void gemm_out(const float* __restrict__ bias, float* __restrict__ out) {
    gemm_body<false>(g_samp, gWu, bias, out, 256, blockIdx.x * 128, blockIdx.y * 128);
}

// ---------------------------------------------------------------------------
// Deformable sampler v5: head-major value layout; x-corner pairs fetched with
// one LDG.128 spanning both (contiguous 64B+64B). Queries processed in pairs
// for softmax/precompute; gather processes 2 points x 2 y-rows per iteration.
// Lane = p2(bit4) | yc(bit3) | xc(bit2) | cs(bits0-1); address =
// rowbase[yc] + xc*dx + cs*16 with dx in {0,64} (exact under clamping).
// ---------------------------------------------------------------------------
__global__ __launch_bounds__(256)
void sampler(const float* __restrict__ refp) {
    __shared__ __align__(16) float smp[8][32][8];
    const unsigned FULL = 0xffffffffu;
    const int h    = threadIdx.x >> 5;
    const int lane = threadIdx.x & 31;
    const int base = blockIdx.x * CHUNK;
    const int b    = (base >= NQ) ? 1 : 0;

    // precompute lane roles
    const int qi = lane >> 4;     // query of the pair
    const int p  = lane & 15;     // point id
    const int l  = p >> 2;        // level
    const int Wl = LVL_W[l];
    const int st = LVL_S[l];

    // gather lane roles
    const int cs = lane & 3;            // 16B chan-slot (8 halves)
    const int xc = (lane >> 2) & 1;     // x corner
    const int yc = (lane >> 3) & 1;     // y corner
    const int p2 = lane >> 4;           // point parity
    const char* vbase = (const char*)g_val + ((size_t)(b * 8 + h) * NV) * 64 + cs * 16;

    for (int i = 0; i < CHUNK; i += 2) {
        const int bq  = base + i;
        const int bq2 = bq + qi;

        // paired softmax: all 32 lanes hold real logits
        float logit = g_attn[(size_t)bq2 * 128 + h * 16 + p];
        float m = logit;
#pragma unroll
        for (int o = 8; o > 0; o >>= 1) m = fmaxf(m, __shfl_xor_sync(FULL, m, o));
        float e = __expf(logit - m);
        float s = e;
#pragma unroll
        for (int o = 8; o > 0; o >>= 1) s += __shfl_xor_sync(FULL, s, o);
        float aw = e / s;

        // per-point precompute (each lane = one point of one query)
        {
            float2 offv = *(const float2*)&g_off[(size_t)bq2 * 256 + h * 32 + 2 * p];
            float2 refv = *(const float2*)&refp[(size_t)bq2 * 8 + 2 * l];

            float x = refv.x * (float)Wl + offv.x - 0.5f;
            float y = refv.y * (float)Wl + offv.y - 0.5f;
            float xf = floorf(x), yf = floorf(y);
            int x0 = (int)xf, y0 = (int)yf;
            float fx = x - xf, fy = y - yf;

            float w00 = (1.0f - fx) * (1.0f - fy) * aw;
            float w10 = fx * (1.0f - fy) * aw;
            float w01 = (1.0f - fx) * fy * aw;
            float w11 = fx * fy * aw;

            bool vx0 = (x0 >= 0) && (x0 < Wl);
            bool vx1 = (x0 + 1 >= 0) && (x0 + 1 < Wl);
            bool vy0 = (y0 >= 0) && (y0 < Wl);
            bool vy1 = (y0 + 1 >= 0) && (y0 + 1 < Wl);
            w00 = (vx0 && vy0) ? w00 : 0.0f;
            w10 = (vx1 && vy0) ? w10 : 0.0f;
            w01 = (vx0 && vy1) ? w01 : 0.0f;
            w11 = (vx1 && vy1) ? w11 : 0.0f;

            int xc0 = min(max(x0, 0), Wl - 1);
            int xc1 = min(max(x0 + 1, 0), Wl - 1);
            int yc0 = min(max(y0, 0), Wl - 1);
            int yc1 = min(max(y0 + 1, 0), Wl - 1);

            // byte offsets within this head's image (64B per pixel)
            int rb0 = (st + yc0 * Wl + xc0) << 6;
            int rb1 = (st + yc1 * Wl + xc0) << 6;
            int dx  = (xc1 - xc0) << 6;   // 0 or 64

            *(float4*)&smp[h][lane][0] =
                make_float4(__int_as_float(rb0), __int_as_float(dx),
                            __int_as_float(rb1), __int_as_float(dx));
            *(float4*)&smp[h][lane][4] = make_float4(w00, w10, w01, w11);
        }
        __syncwarp();

        // gather per query: 8 iterations of (2 points x 2 y-rows)
#pragma unroll
        for (int qq = 0; qq < 2; qq++) {
            float acc[8];
#pragma unroll
            for (int k = 0; k < 8; k++) acc[k] = 0.0f;

#pragma unroll
            for (int pp = 0; pp < 16; pp += 2) {
                const float* sp = smp[h][qq * 16 + pp + p2];
                float2 rbdx = *(const float2*)&sp[yc * 2];
                float w = sp[4 + yc * 2 + xc];
                int off = __float_as_int(rbdx.x) + xc * __float_as_int(rbdx.y);
                uint4 raw = __ldg((const uint4*)(vbase + off));
                float2 v0 = __half22float2(*(const __half2*)&raw.x);
                float2 v1 = __half22float2(*(const __half2*)&raw.y);
                float2 v2 = __half22float2(*(const __half2*)&raw.z);
                float2 v3 = __half22float2(*(const __half2*)&raw.w);
                acc[0] = fmaf(w, v0.x, acc[0]);
                acc[1] = fmaf(w, v0.y, acc[1]);
                acc[2] = fmaf(w, v1.x, acc[2]);
                acc[3] = fmaf(w, v1.y, acc[3]);
                acc[4] = fmaf(w, v2.x, acc[4]);
                acc[5] = fmaf(w, v2.y, acc[5]);
                acc[6] = fmaf(w, v3.x, acc[6]);
                acc[7] = fmaf(w, v3.y, acc[7]);
            }

            // reduce over xc (4), yc (8), p2 (16); channels stay per-cs
#pragma unroll
            for (int o = 4; o <= 16; o <<= 1)
#pragma unroll
                for (int k = 0; k < 8; k++)
                    acc[k] += __shfl_xor_sync(FULL, acc[k], o);

            if (lane < 4) {
                size_t o8 = (size_t)(bq + qq) * 256 + h * 32 + lane * 8;
                *(uint4*)&g_samp[o8] =
                    make_uint4(tf32r(acc[0]), tf32r(acc[1]), tf32r(acc[2]), tf32r(acc[3]));
                *(uint4*)&g_samp[o8 + 4] =
                    make_uint4(tf32r(acc[4]), tf32r(acc[5]), tf32r(acc[6]), tf32r(acc[7]));
            }
        }
        __syncwarp();   // guard smp reuse across pair iterations
    }
}

// ---------------------------------------------------------------------------
// kernel_launch
// Inputs: 0 query, 1 value, 2 reference_points, 3 spatial_shapes,
// 4 W_off, 5 b_off, 6 W_attn, 7 b_attn, 8 W_v, 9 b_v, 10 W_out, 11 b_out
// ---------------------------------------------------------------------------
extern "C" void kernel_launch(void* const* d_in, const int* in_sizes, int n_in,
                              void* d_out, int out_size) {
    const float* query = (const float*)d_in[0];
    const float* value = (const float*)d_in[1];
    const float* refp  = (const float*)d_in[2];
    const float* W_off = (const float*)d_in[4];
    const float* b_off = (const float*)d_in[5];
    const float* W_att = (const float*)d_in[6];
    const float* b_att = (const float*)d_in[7];
    const float* W_v   = (const float*)d_in[8];
    const float* b_v   = (const float*)d_in[9];
    const float* W_out = (const float*)d_in[10];
    const float* b_out = (const float*)d_in[11];
    float* out = (float*)d_out;

    cudaFuncSetAttribute(gemm_vqa, cudaFuncAttributeMaxDynamicSharedMemorySize, DSMEM_BYTES);
    cudaFuncSetAttribute(gemm_out, cudaFuncAttributeMaxDynamicSharedMemorySize, DSMEM_BYTES);

    dim3 blk(256);

    convert_acts<<<2 * (ACT_WORDS / 256), blk>>>(query, value);
    convert_wts<<<224, blk>>>(W_v, W_off, W_att, W_out);

    gemm_vqa<<<dim3(MROWS / 128, 5), blk, DSMEM_BYTES>>>(b_v, b_off, b_att);
    sampler<<<MROWS / CHUNK, blk>>>(refp);
    gemm_out<<<dim3(MROWS / 128, 2), blk, DSMEM_BYTES>>>(b_out, out);
}